// round 13
// baseline (speedup 1.0000x reference)
#include <cuda_runtime.h>
#include <cuda_bf16.h>
#include <cuda_fp16.h>
#include <math.h>
#include <stdint.h>

#define NN 50000
#define NE 800000
#define DH 128
#define DO 47
#define MM (2*NN)
#define OPB (NN*(DH+DO+DO))
#define NB_SCAN ((NN + 1023)/1024)

// ---------------- scratch ----------------
__device__ float g_x2[MM*DH];     // x2 fp16 image; later reused as h2 fp16 image
__device__ float g_t [MM*DH];     // t as fp16x2 (MM x 64 u32)
__device__ float g_r [MM*DH];
__device__ float g_h [MM*DH];     // h1 fp16 image (100096 rows x 256B)
__device__ float g_t2[MM*DO];
__device__ float g_r2[MM*DO];
__device__ int   g_deg[NN];
__device__ int   g_off[NN+1];
__device__ int   g_pos[NN];
__device__ int   g_csr[NE];
__device__ int   g_bsum[64];
__device__ int   g_flag[64];
// fp16 weight images, [g-slice 32KB][n row 256B] chunk-swizzled
__device__ __align__(16) uint8_t g_wimg[2*65536 + 2*65536 + 2*32768];

// ---------------- helpers ----------------
__device__ __forceinline__ uint32_t smem_u32(const void* p) {
    uint32_t a;
    asm("{ .reg .u64 t; cvta.to.shared.u64 t, %1; cvt.u32.u64 %0, t; }" : "=r"(a) : "l"(p));
    return a;
}
__device__ __forceinline__ void ldsm4(uint32_t* r, uint32_t addr) {
    asm volatile("ldmatrix.sync.aligned.m8n8.x4.shared.b16 {%0,%1,%2,%3}, [%4];"
        : "=r"(r[0]), "=r"(r[1]), "=r"(r[2]), "=r"(r[3]) : "r"(addr));
}
__device__ __forceinline__ void mma16816(float* c, const uint32_t* a, uint32_t b0, uint32_t b1) {
    asm volatile("mma.sync.aligned.m16n8k16.row.col.f32.f16.f16.f32 "
        "{%0,%1,%2,%3}, {%4,%5,%6,%7}, {%8,%9}, {%0,%1,%2,%3};"
        : "+f"(c[0]), "+f"(c[1]), "+f"(c[2]), "+f"(c[3])
        : "r"(a[0]), "r"(a[1]), "r"(a[2]), "r"(a[3]), "r"(b0), "r"(b1));
}
__device__ __forceinline__ uint32_t pack_h2(float a, float b) {
    __half2 h = __floats2half2_rn(a, b);
    return *(uint32_t*)&h;
}
__device__ __forceinline__ void cvt_hilo16(const float* v, uint32_t* hp, uint32_t* lp) {
    #pragma unroll
    for (int p = 0; p < 4; p++) {
        __half2 h2 = __floats2half2_rn(v[2*p], v[2*p+1]);
        float l0 = v[2*p]   - __low2float(h2);
        float l1 = v[2*p+1] - __high2float(h2);
        __half2 l2 = __floats2half2_rn(l0, l1);
        hp[p] = *(uint32_t*)&h2;
        lp[p] = *(uint32_t*)&l2;
    }
}
#define CP16(sm, gp) asm volatile("cp.async.cg.shared.global [%0], [%1], 16;" :: "r"(sm), "l"(gp))
#define CP_COMMIT()  asm volatile("cp.async.commit_group;" ::: "memory")
#define CP_WAIT0()   asm volatile("cp.async.wait_group 0;" ::: "memory")

// ---------------- weight image writer: [g 32KB][n][256B] ----------------
__device__ __forceinline__ void wconv_item(int id,
        const float* Wl0, const float* Wr0, const float* Wl1, const float* Wr1,
        const float* Wl2, const float* Wr2) {
    const float* src = nullptr;
    uint8_t *imgHi, *imgLo;
    int row, c8;
    if (id < 4096) {
        row = id >> 4; c8 = id & 15;
        imgHi = g_wimg;          imgLo = g_wimg + 65536;
        src = (row < 128) ? (Wl0 + (size_t)row*128) : (Wr0 + (size_t)(row-128)*128);
    } else if (id < 8192) {
        id -= 4096; row = id >> 4; c8 = id & 15;
        imgHi = g_wimg + 131072; imgLo = g_wimg + 196608;
        src = (row < 128) ? (Wl1 + (size_t)row*128) : (Wr1 + (size_t)(row-128)*128);
    } else if (id < 10240) {
        id -= 8192; row = id >> 4; c8 = id & 15;
        imgHi = g_wimg + 262144; imgLo = g_wimg + 294912;
        if (row < 47)                     src = Wl2 + (size_t)row*128;
        else if (row >= 64 && row < 111)  src = Wr2 + (size_t)(row-64)*128;
        else                              src = nullptr;
    } else return;
    float v[8];
    #pragma unroll
    for (int j = 0; j < 8; j++) v[j] = src ? src[c8*8 + j] : 0.f;
    uint32_t hp[4], lp[4];
    cvt_hilo16(v, hp, lp);
    int gsl = row >> 7, n = row & 127;
    uint32_t off = (uint32_t)gsl*32768u + (uint32_t)n*256u
                 + (uint32_t)((c8 ^ (n & 7)) << 4);
    *(uint4*)(imgHi + off) = make_uint4(hp[0], hp[1], hp[2], hp[3]);
    *(uint4*)(imgLo + off) = make_uint4(lp[0], lp[1], lp[2], lp[3]);
}

// ---------------- prep: noise->fp16 image + wconv + zero fused ----------------
#define NOISE_BLOCKS (NN/8)
#define WCONV_BLOCKS 40
#define ZERO_BLOCKS ((NN + 255)/256)
__global__ void k_prep(const float* __restrict__ x, const float* __restrict__ noise,
                       const float* Wl0, const float* Wr0,
                       const float* Wl1, const float* Wr1,
                       const float* Wl2, const float* Wr2) {
    if (blockIdx.x < NOISE_BLOCKS) {
        int i = (blockIdx.x*blockDim.x + threadIdx.x) >> 5;
        int lane = threadIdx.x & 31;
        const float4 nv = *(const float4*)(noise + (size_t)i*DH + lane*4);
        float ss = nv.x*nv.x + nv.y*nv.y + nv.z*nv.z + nv.w*nv.w;
        #pragma unroll
        for (int o = 16; o; o >>= 1) ss += __shfl_xor_sync(0xffffffffu, ss, o);
        float sc = 0.1f / fmaxf(sqrtf(ss), 1e-12f);
        float4 xv = *(const float4*)(x + (size_t)i*DH + lane*4);
        float4 xn;
        xn.x = xv.x + ((xv.x>0.f)?1.f:((xv.x<0.f)?-1.f:0.f)) * nv.x * sc;
        xn.y = xv.y + ((xv.y>0.f)?1.f:((xv.y<0.f)?-1.f:0.f)) * nv.y * sc;
        xn.z = xv.z + ((xv.z>0.f)?1.f:((xv.z<0.f)?-1.f:0.f)) * nv.z * sc;
        xn.w = xv.w + ((xv.w>0.f)?1.f:((xv.w<0.f)?-1.f:0.f)) * nv.w * sc;
        // write fp16 image rows i (clean) and NN+i (noisy)
        uint32_t* himg = (uint32_t*)g_x2;
        int c8 = lane >> 1, half = (lane & 1) << 3;
        uint32_t offc = (uint32_t)i*64u      + (((uint32_t)(c8 ^ (i      & 7)) << 4) + half)/4u;
        uint32_t offn = (uint32_t)(NN+i)*64u + (((uint32_t)(c8 ^ ((NN+i) & 7)) << 4) + half)/4u;
        *(uint2*)(himg + offc) = make_uint2(pack_h2(xv.x, xv.y), pack_h2(xv.z, xv.w));
        *(uint2*)(himg + offn) = make_uint2(pack_h2(xn.x, xn.y), pack_h2(xn.z, xn.w));
    } else if (blockIdx.x < NOISE_BLOCKS + WCONV_BLOCKS) {
        int id = (blockIdx.x - NOISE_BLOCKS)*blockDim.x + threadIdx.x;
        wconv_item(id, Wl0, Wr0, Wl1, Wr1, Wl2, Wr2);
    } else {
        int id = (blockIdx.x - NOISE_BLOCKS - WCONV_BLOCKS)*blockDim.x + threadIdx.x;
        if (id < NN) g_deg[id] = 0;
        if (id < 64) { g_bsum[id] = 0; g_flag[id] = 0; }
    }
}

// ---------------- CSR build ----------------
__global__ void k_hist(const int* __restrict__ ei) {
    int e = blockIdx.x*blockDim.x + threadIdx.x;
    if (e < NE) atomicAdd(&g_deg[ei[NE + e]], 1);
}
// single-pass chained scan over 49 blocks (all co-resident on 148 SMs)
__global__ void k_scan() {
    __shared__ int ws[32];
    __shared__ int sprefix;
    int tid = threadIdx.x, lane = tid & 31, w = tid >> 5, b = blockIdx.x;
    int gid = b*1024 + tid;
    int v = (gid < NN) ? g_deg[gid] : 0;
    int s = v;
    #pragma unroll
    for (int o = 1; o < 32; o <<= 1) {
        int t = __shfl_up_sync(0xffffffffu, s, o);
        if (lane >= o) s += t;
    }
    if (lane == 31) ws[w] = s;
    __syncthreads();
    if (w == 0) {
        int x = ws[lane];
        #pragma unroll
        for (int o = 1; o < 32; o <<= 1) {
            int t = __shfl_up_sync(0xffffffffu, x, o);
            if (lane >= o) x += t;
        }
        ws[lane] = x;
    }
    __syncthreads();
    if (w > 0) s += ws[w-1];
    int btotal = ws[31];
    if (tid == 0) {
        int prev = 0;
        if (b > 0) {
            while (atomicAdd(&g_flag[b-1], 0) == 0) { }
            prev = *(volatile int*)&g_bsum[b-1];
        }
        sprefix = prev;
        *(volatile int*)&g_bsum[b] = prev + btotal;
        __threadfence();
        atomicExch(&g_flag[b], 1);
    }
    __syncthreads();
    int incl = s + sprefix;
    if (gid < NN) {
        g_off[gid+1] = incl;
        g_pos[gid]   = incl - v;
    }
    if (gid == 0) g_off[0] = 0;
}
__global__ void k_fill(const int* __restrict__ ei) {
    int e = blockIdx.x*blockDim.x + threadIdx.x;
    if (e < NE) {
        int dst = ei[NE + e];
        int p = atomicAdd(&g_pos[dst], 1);
        g_csr[p] = ei[e];
    }
}

// ---------------- 2-term fp16 GEMM: A*(Bh+Bl), 96KB smem, 2 CTA/SM ----------------
// smem: A fp16 [0,32K), Bh [32K,64K), Bl [64K,96K). All fills are cp.async raw copies.
// A always from pre-swizzled fp16 image.
// !SPLIT47: g==0 -> out0 packed fp16x2 (stride 64 u32); g==1 -> out1 fp32 (stride 128)
// SPLIT47:  cols 0-63 -> out0 fp32 (stride DO), 64-127 -> out1 (stride DO)
template<bool SPLIT47>
__global__ void __launch_bounds__(256, 2) k_gemm_mma(
    const uint8_t* __restrict__ Aimg,
    const uint8_t* __restrict__ imgHi, const uint8_t* __restrict__ imgLo,
    void* __restrict__ out0, float* __restrict__ out1, int M)
{
    extern __shared__ char smem[];
    const int tid = threadIdx.x;
    const int bm = blockIdx.x * 128;
    const int g  = blockIdx.y;
    uint32_t sb = smem_u32(smem);

    {
        const uint4* sa = (const uint4*)(Aimg + (size_t)bm*256);
        const uint4* bh = (const uint4*)(imgHi + (size_t)g*32768);
        const uint4* bl = (const uint4*)(imgLo + (size_t)g*32768);
        #pragma unroll
        for (int i = 0; i < 8; i++) {
            int id = tid + i*256;
            CP16(sb +          (uint32_t)id*16u, sa + id);
            CP16(sb + 32768u + (uint32_t)id*16u, bh + id);
            CP16(sb + 65536u + (uint32_t)id*16u, bl + id);
        }
        CP_COMMIT();
        CP_WAIT0();
    }
    __syncthreads();

    const int lane = tid & 31, w = tid >> 5;
    const int tm = (w >> 1) * 32, tn = (w & 1) * 64;
    const int lrow = lane & 15;
    const uint32_t lsel = (uint32_t)(lane >> 4);

    float acc[2][8][4];
    #pragma unroll
    for (int a = 0; a < 2; a++)
        #pragma unroll
        for (int b = 0; b < 8; b++)
            #pragma unroll
            for (int c = 0; c < 4; c++) acc[a][b][c] = 0.f;

    #pragma unroll
    for (int k16 = 0; k16 < 8; k16++) {
        const uint32_t c8 = (uint32_t)(k16*2) + lsel;
        uint32_t a[2][4];
        #pragma unroll
        for (int mt = 0; mt < 2; mt++) {
            int row = tm + mt*16 + lrow;
            ldsm4(a[mt], sb + (uint32_t)row*256u + ((c8 ^ (uint32_t)(row & 7)) << 4));
        }
        #pragma unroll
        for (int term = 0; term < 2; term++) {
            uint32_t bbase = sb + 32768u + (uint32_t)term*32768u;
            uint32_t b[4][4];
            #pragma unroll
            for (int bt = 0; bt < 4; bt++) {
                int n = tn + bt*16 + lrow;
                ldsm4(b[bt], bbase + (uint32_t)n*256u + ((c8 ^ (uint32_t)(n & 7)) << 4));
            }
            #pragma unroll
            for (int mt = 0; mt < 2; mt++)
                #pragma unroll
                for (int bt = 0; bt < 4; bt++) {
                    mma16816(acc[mt][bt*2+0], a[mt], b[bt][0], b[bt][2]);
                    mma16816(acc[mt][bt*2+1], a[mt], b[bt][1], b[bt][3]);
                }
        }
    }

    if constexpr (!SPLIT47) {
        if (g == 0) {   // t: packed fp16x2
            uint32_t* dst = (uint32_t*)out0;
            #pragma unroll
            for (int mt = 0; mt < 2; mt++) {
                int r0 = bm + tm + mt*16 + (lane >> 2);
                int r1 = r0 + 8;
                #pragma unroll
                for (int nt = 0; nt < 8; nt++) {
                    int cp = (tn + nt*8 + (lane & 3)*2) >> 1;
                    if (r0 < M) dst[(size_t)r0*64 + cp] = pack_h2(acc[mt][nt][0], acc[mt][nt][1]);
                    if (r1 < M) dst[(size_t)r1*64 + cp] = pack_h2(acc[mt][nt][2], acc[mt][nt][3]);
                }
            }
        } else {        // r: fp32
            #pragma unroll
            for (int mt = 0; mt < 2; mt++) {
                int r0 = bm + tm + mt*16 + (lane >> 2);
                int r1 = r0 + 8;
                #pragma unroll
                for (int nt = 0; nt < 8; nt++) {
                    int col = tn + nt*8 + (lane & 3)*2;
                    if (r0 < M) *(float2*)(out1 + (size_t)r0*128 + col)
                        = make_float2(acc[mt][nt][0], acc[mt][nt][1]);
                    if (r1 < M) *(float2*)(out1 + (size_t)r1*128 + col)
                        = make_float2(acc[mt][nt][2], acc[mt][nt][3]);
                }
            }
        }
    } else {
        float* dst = (w & 1) ? out1 : (float*)out0;
        #pragma unroll
        for (int mt = 0; mt < 2; mt++) {
            int r0 = bm + tm + mt*16 + (lane >> 2);
            int r1 = r0 + 8;
            #pragma unroll
            for (int nt = 0; nt < 8; nt++) {
                int cl = nt*8 + (lane & 3)*2;
                if (cl < DO) {
                    if (r0 < M) dst[(size_t)r0*DO + cl] = acc[mt][nt][0];
                    if (r1 < M) dst[(size_t)r1*DO + cl] = acc[mt][nt][2];
                }
                if (cl + 1 < DO) {
                    if (r0 < M) dst[(size_t)r0*DO + cl + 1] = acc[mt][nt][1];
                    if (r1 < M) dst[(size_t)r1*DO + cl + 1] = acc[mt][nt][3];
                }
            }
        }
    }
}

// ---------------- branch-merged 128-dim mean-agg + bias + self + relu ----------------
__global__ void k_agg128(const uint32_t* __restrict__ t, const float* __restrict__ r,
                         const float* __restrict__ bias,
                         uint32_t* __restrict__ himg, float* __restrict__ dout)
{
    int i = (blockIdx.x*blockDim.x + threadIdx.x) >> 5;
    int lane = threadIdx.x & 31;
    if (i >= NN) return;
    int e0 = g_off[i], e1 = g_off[i+1];
    float4 ac = make_float4(0.f,0.f,0.f,0.f);
    float4 an = make_float4(0.f,0.f,0.f,0.f);
    int e = e0;
    for (; e + 2 <= e1; e += 2) {
        int j0 = g_csr[e], j1 = g_csr[e+1];
        uint2 c0 = *(const uint2*)(t + ((size_t)j0        << 6) + (lane << 1));
        uint2 n0 = *(const uint2*)(t + ((size_t)(NN + j0) << 6) + (lane << 1));
        uint2 c1 = *(const uint2*)(t + ((size_t)j1        << 6) + (lane << 1));
        uint2 n1 = *(const uint2*)(t + ((size_t)(NN + j1) << 6) + (lane << 1));
        float2 cl0 = __half22float2(*(__half2*)&c0.x), ch0 = __half22float2(*(__half2*)&c0.y);
        float2 nl0 = __half22float2(*(__half2*)&n0.x), nh0 = __half22float2(*(__half2*)&n0.y);
        float2 cl1 = __half22float2(*(__half2*)&c1.x), ch1 = __half22float2(*(__half2*)&c1.y);
        float2 nl1 = __half22float2(*(__half2*)&n1.x), nh1 = __half22float2(*(__half2*)&n1.y);
        ac.x += cl0.x + cl1.x; ac.y += cl0.y + cl1.y;
        ac.z += ch0.x + ch1.x; ac.w += ch0.y + ch1.y;
        an.x += nl0.x + nl1.x; an.y += nl0.y + nl1.y;
        an.z += nh0.x + nh1.x; an.w += nh0.y + nh1.y;
    }
    if (e < e1) {
        int j = g_csr[e];
        uint2 c = *(const uint2*)(t + ((size_t)j        << 6) + (lane << 1));
        uint2 n = *(const uint2*)(t + ((size_t)(NN + j) << 6) + (lane << 1));
        float2 cl = __half22float2(*(__half2*)&c.x), ch = __half22float2(*(__half2*)&c.y);
        float2 nl = __half22float2(*(__half2*)&n.x), nh = __half22float2(*(__half2*)&n.y);
        ac.x += cl.x; ac.y += cl.y; ac.z += ch.x; ac.w += ch.y;
        an.x += nl.x; an.y += nl.y; an.z += nh.x; an.w += nh.y;
    }
    float inv = (e1 > e0) ? 1.f/(float)(e1 - e0) : 0.f;
    float4 bb = *(const float4*)(bias + (lane << 2));
    float4 rc = *(const float4*)(r + ((size_t)i        << 7) + (lane << 2));
    float4 rn = *(const float4*)(r + ((size_t)(NN + i) << 7) + (lane << 2));
    float4 oc, on;
    oc.x = fmaxf(fmaf(ac.x, inv, bb.x + rc.x), 0.f);
    oc.y = fmaxf(fmaf(ac.y, inv, bb.y + rc.y), 0.f);
    oc.z = fmaxf(fmaf(ac.z, inv, bb.z + rc.z), 0.f);
    oc.w = fmaxf(fmaf(ac.w, inv, bb.w + rc.w), 0.f);
    on.x = fmaxf(fmaf(an.x, inv, bb.x + rn.x), 0.f);
    on.y = fmaxf(fmaf(an.y, inv, bb.y + rn.y), 0.f);
    on.z = fmaxf(fmaf(an.z, inv, bb.z + rn.z), 0.f);
    on.w = fmaxf(fmaf(an.w, inv, bb.w + rn.w), 0.f);
    if (himg) {
        int c8 = lane >> 1, half = (lane & 1) << 3;
        uint32_t offc = (uint32_t)i*64u      + (((uint32_t)(c8 ^ (i      & 7)) << 4) + half)/4u;
        uint32_t offn = (uint32_t)(NN+i)*64u + (((uint32_t)(c8 ^ ((NN+i) & 7)) << 4) + half)/4u;
        *(uint2*)(himg + offc) = make_uint2(pack_h2(oc.x, oc.y), pack_h2(oc.z, oc.w));
        *(uint2*)(himg + offn) = make_uint2(pack_h2(on.x, on.y), pack_h2(on.z, on.w));
    }
    if (dout) {
        *(float4*)(dout + (size_t)i*DH + (lane << 2)) = oc;
        *(float4*)(dout + (size_t)OPB + (size_t)i*DH + (lane << 2)) = on;
    }
}

// ---------------- branch-merged 47-dim agg + log_softmax ----------------
__global__ void k_agg47(const float* __restrict__ t2, const float* __restrict__ r2,
                        const float* __restrict__ bias, float* __restrict__ dout)
{
    int i = (blockIdx.x*blockDim.x + threadIdx.x) >> 5;
    int lane = threadIdx.x & 31;
    if (i >= NN) return;
    int f0 = lane*2, f1 = lane*2 + 1;
    bool v0 = (f0 < DO), v1 = (f1 < DO);
    int e0 = g_off[i], e1 = g_off[i+1];
    float ac0 = 0.f, ac1 = 0.f, an0 = 0.f, an1 = 0.f;
    for (int e = e0; e < e1; e++) {
        int j = g_csr[e];
        const float* rowC = t2 + (size_t)j        * DO;
        const float* rowN = t2 + (size_t)(NN + j) * DO;
        if (v0) { ac0 += rowC[f0]; an0 += rowN[f0]; }
        if (v1) { ac1 += rowC[f1]; an1 += rowN[f1]; }
    }
    float inv = (e1 > e0) ? 1.f/(float)(e1 - e0) : 0.f;
    float b0 = v0 ? bias[f0] : 0.f;
    float b1 = v1 ? bias[f1] : 0.f;
    float zc0 = v0 ? fmaf(ac0, inv, b0 + r2[(size_t)i*DO + f0]) : -INFINITY;
    float zc1 = v1 ? fmaf(ac1, inv, b1 + r2[(size_t)i*DO + f1]) : -INFINITY;
    float zn0 = v0 ? fmaf(an0, inv, b0 + r2[(size_t)(NN+i)*DO + f0]) : -INFINITY;
    float zn1 = v1 ? fmaf(an1, inv, b1 + r2[(size_t)(NN+i)*DO + f1]) : -INFINITY;
    float mc = fmaxf(zc0, zc1), mn = fmaxf(zn0, zn1);
    #pragma unroll
    for (int o = 16; o; o >>= 1) {
        mc = fmaxf(mc, __shfl_xor_sync(0xffffffffu, mc, o));
        mn = fmaxf(mn, __shfl_xor_sync(0xffffffffu, mn, o));
    }
    float sc = (v0 ? expf(zc0 - mc) : 0.f) + (v1 ? expf(zc1 - mc) : 0.f);
    float sn = (v0 ? expf(zn0 - mn) : 0.f) + (v1 ? expf(zn1 - mn) : 0.f);
    #pragma unroll
    for (int o = 16; o; o >>= 1) {
        sc += __shfl_xor_sync(0xffffffffu, sc, o);
        sn += __shfl_xor_sync(0xffffffffu, sn, o);
    }
    float lc = mc + logf(sc), ln = mn + logf(sn);
    float* ycb = dout + (size_t)NN*DH                       + (size_t)i*DO;
    float* zcb = dout + (size_t)NN*(DH + DO)                + (size_t)i*DO;
    float* ynb = dout + (size_t)OPB + (size_t)NN*DH         + (size_t)i*DO;
    float* znb = dout + (size_t)OPB + (size_t)NN*(DH + DO)  + (size_t)i*DO;
    if (v0) { zcb[f0] = zc0; ycb[f0] = zc0 - lc; znb[f0] = zn0; ynb[f0] = zn0 - ln; }
    if (v1) { zcb[f1] = zc1; ycb[f1] = zc1 - lc; znb[f1] = zn1; ynb[f1] = zn1 - ln; }
}

// ---------------- orchestration ----------------
extern "C" void kernel_launch(void* const* d_in, const int* in_sizes, int n_in,
                              void* d_out, int out_size)
{
    const float* x     = (const float*)d_in[0];
    const int*   ei    = (const int*)  d_in[1];
    const float* noise = (const float*)d_in[2];
    const float* Wl0   = (const float*)d_in[3];
    const float* bl0   = (const float*)d_in[4];
    const float* Wr0   = (const float*)d_in[5];
    const float* Wl1   = (const float*)d_in[6];
    const float* bl1   = (const float*)d_in[7];
    const float* Wr1   = (const float*)d_in[8];
    const float* Wl2   = (const float*)d_in[9];
    const float* bl2   = (const float*)d_in[10];
    const float* Wr2   = (const float*)d_in[11];
    float* out = (float*)d_out;

    float *px2, *pt, *pr, *ph, *pt2, *pr2;
    uint8_t* pw;
    cudaGetSymbolAddress((void**)&px2, g_x2);
    cudaGetSymbolAddress((void**)&pt,  g_t);
    cudaGetSymbolAddress((void**)&pr,  g_r);
    cudaGetSymbolAddress((void**)&ph,  g_h);
    cudaGetSymbolAddress((void**)&pt2, g_t2);
    cudaGetSymbolAddress((void**)&pr2, g_r2);
    cudaGetSymbolAddress((void**)&pw,  g_wimg);

    const int SM = 98304;   // 96KB -> 2 CTAs/SM (measured-best config)
    cudaFuncSetAttribute((const void*)k_gemm_mma<false>, cudaFuncAttributeMaxDynamicSharedMemorySize, SM);
    cudaFuncSetAttribute((const void*)k_gemm_mma<true>,  cudaFuncAttributeMaxDynamicSharedMemorySize, SM);

    int gBlocks = (MM + 127)/128;
    dim3 gBig(gBlocks, 2);
    dim3 gSml(gBlocks, 1);
    int aggBlocks = (NN*32 + 255)/256;

    // idx 0: noise->x2 fp16 image + wconv + zero
    k_prep<<<NOISE_BLOCKS + WCONV_BLOCKS + ZERO_BLOCKS, 256>>>(
        x, noise, Wl0, Wr0, Wl1, Wr1, Wl2, Wr2);
    // idx 1: histogram; idx 2: chained scan (one launch)
    k_hist<<<(NE + 255)/256, 256>>>(ei);
    k_scan<<<NB_SCAN, 1024>>>();
    // idx 3: layer-0 GEMM (ncu capture target; A from x2 image)
    k_gemm_mma<false><<<gBig, 256, SM>>>((const uint8_t*)px2,
                                         pw, pw + 65536, pt, pr, MM);
    // idx 4: CSR fill
    k_fill<<<(NE + 255)/256, 256>>>(ei);
    // layer 0 agg -> h1 fp16 image (g_h)
    k_agg128<<<aggBlocks, 256>>>((const uint32_t*)pt, pr, bl0, (uint32_t*)ph, nullptr);
    // layer 1 (A from h1 image); agg writes d_out fp32 + h2 fp16 image (g_x2)
    k_gemm_mma<false><<<gBig, 256, SM>>>((const uint8_t*)ph,
                                         pw + 131072, pw + 196608, pt, pr, MM);
    k_agg128<<<aggBlocks, 256>>>((const uint32_t*)pt, pr, bl1, (uint32_t*)px2, out);
    // layer 2 (A from h2 image)
    k_gemm_mma<true><<<gSml, 256, SM>>>((const uint8_t*)px2,
                                        pw + 262144, pw + 294912, pt2, pr2, MM);
    k_agg47<<<aggBlocks, 256>>>(pt2, pr2, bl2, out);
}

// round 14
// speedup vs baseline: 1.1609x; 1.1609x over previous
#include <cuda_runtime.h>
#include <cuda_bf16.h>
#include <cuda_fp16.h>
#include <math.h>
#include <stdint.h>

#define NN 50000
#define NE 800000
#define DH 128
#define DO 47
#define MM (2*NN)
#define OPB (NN*(DH+DO+DO))
#define NB_SCAN ((NN + 1023)/1024)

// ---------------- scratch ----------------
__device__ float g_x2[MM*DH];     // x2 fp16 image; later reused as h2 fp16 image
__device__ float g_t [MM*DH];     // t as fp16x2 (MM x 64 u32)
__device__ float g_r [MM*DH];
__device__ float g_h [MM*DH];     // h1 fp16 image (100096 rows x 256B)
__device__ float g_t2[MM*DO];
__device__ float g_r2[MM*DO];
__device__ int   g_deg[NN];
__device__ int   g_off[NN+1];
__device__ int   g_pos[NN];
__device__ int   g_csr[NE];
__device__ int   g_bsum[64];
// fp16 weight images, [g-slice 32KB][n row 256B] chunk-swizzled
__device__ __align__(16) uint8_t g_wimg[2*65536 + 2*65536 + 2*32768];

// ---------------- helpers ----------------
__device__ __forceinline__ uint32_t smem_u32(const void* p) {
    uint32_t a;
    asm("{ .reg .u64 t; cvta.to.shared.u64 t, %1; cvt.u32.u64 %0, t; }" : "=r"(a) : "l"(p));
    return a;
}
__device__ __forceinline__ void ldsm4(uint32_t* r, uint32_t addr) {
    asm volatile("ldmatrix.sync.aligned.m8n8.x4.shared.b16 {%0,%1,%2,%3}, [%4];"
        : "=r"(r[0]), "=r"(r[1]), "=r"(r[2]), "=r"(r[3]) : "r"(addr));
}
__device__ __forceinline__ void mma16816(float* c, const uint32_t* a, uint32_t b0, uint32_t b1) {
    asm volatile("mma.sync.aligned.m16n8k16.row.col.f32.f16.f16.f32 "
        "{%0,%1,%2,%3}, {%4,%5,%6,%7}, {%8,%9}, {%0,%1,%2,%3};"
        : "+f"(c[0]), "+f"(c[1]), "+f"(c[2]), "+f"(c[3])
        : "r"(a[0]), "r"(a[1]), "r"(a[2]), "r"(a[3]), "r"(b0), "r"(b1));
}
__device__ __forceinline__ uint32_t pack_h2(float a, float b) {
    __half2 h = __floats2half2_rn(a, b);
    return *(uint32_t*)&h;
}
__device__ __forceinline__ void cvt_hilo16(const float* v, uint32_t* hp, uint32_t* lp) {
    #pragma unroll
    for (int p = 0; p < 4; p++) {
        __half2 h2 = __floats2half2_rn(v[2*p], v[2*p+1]);
        float l0 = v[2*p]   - __low2float(h2);
        float l1 = v[2*p+1] - __high2float(h2);
        __half2 l2 = __floats2half2_rn(l0, l1);
        hp[p] = *(uint32_t*)&h2;
        lp[p] = *(uint32_t*)&l2;
    }
}
#define CP16(sm, gp) asm volatile("cp.async.cg.shared.global [%0], [%1], 16;" :: "r"(sm), "l"(gp))
#define CP_COMMIT()  asm volatile("cp.async.commit_group;" ::: "memory")
#define CP_WAIT0()   asm volatile("cp.async.wait_group 0;" ::: "memory")

// ---------------- weight image writer: [g 32KB][n][256B] ----------------
__device__ __forceinline__ void wconv_item(int id,
        const float* Wl0, const float* Wr0, const float* Wl1, const float* Wr1,
        const float* Wl2, const float* Wr2) {
    const float* src = nullptr;
    uint8_t *imgHi, *imgLo;
    int row, c8;
    if (id < 4096) {
        row = id >> 4; c8 = id & 15;
        imgHi = g_wimg;          imgLo = g_wimg + 65536;
        src = (row < 128) ? (Wl0 + (size_t)row*128) : (Wr0 + (size_t)(row-128)*128);
    } else if (id < 8192) {
        id -= 4096; row = id >> 4; c8 = id & 15;
        imgHi = g_wimg + 131072; imgLo = g_wimg + 196608;
        src = (row < 128) ? (Wl1 + (size_t)row*128) : (Wr1 + (size_t)(row-128)*128);
    } else if (id < 10240) {
        id -= 8192; row = id >> 4; c8 = id & 15;
        imgHi = g_wimg + 262144; imgLo = g_wimg + 294912;
        if (row < 47)                     src = Wl2 + (size_t)row*128;
        else if (row >= 64 && row < 111)  src = Wr2 + (size_t)(row-64)*128;
        else                              src = nullptr;
    } else return;
    float v[8];
    #pragma unroll
    for (int j = 0; j < 8; j++) v[j] = src ? src[c8*8 + j] : 0.f;
    uint32_t hp[4], lp[4];
    cvt_hilo16(v, hp, lp);
    int gsl = row >> 7, n = row & 127;
    uint32_t off = (uint32_t)gsl*32768u + (uint32_t)n*256u
                 + (uint32_t)((c8 ^ (n & 7)) << 4);
    *(uint4*)(imgHi + off) = make_uint4(hp[0], hp[1], hp[2], hp[3]);
    *(uint4*)(imgLo + off) = make_uint4(lp[0], lp[1], lp[2], lp[3]);
}

// ---------------- prep: noise->fp16 image + wconv + zero fused ----------------
#define NOISE_BLOCKS (NN/8)
#define WCONV_BLOCKS 40
#define ZERO_BLOCKS ((NN + 255)/256)
__global__ void k_prep(const float* __restrict__ x, const float* __restrict__ noise,
                       const float* Wl0, const float* Wr0,
                       const float* Wl1, const float* Wr1,
                       const float* Wl2, const float* Wr2) {
    if (blockIdx.x < NOISE_BLOCKS) {
        int i = (blockIdx.x*blockDim.x + threadIdx.x) >> 5;
        int lane = threadIdx.x & 31;
        const float4 nv = *(const float4*)(noise + (size_t)i*DH + lane*4);
        float ss = nv.x*nv.x + nv.y*nv.y + nv.z*nv.z + nv.w*nv.w;
        #pragma unroll
        for (int o = 16; o; o >>= 1) ss += __shfl_xor_sync(0xffffffffu, ss, o);
        float sc = 0.1f / fmaxf(sqrtf(ss), 1e-12f);
        float4 xv = *(const float4*)(x + (size_t)i*DH + lane*4);
        float4 xn;
        xn.x = xv.x + ((xv.x>0.f)?1.f:((xv.x<0.f)?-1.f:0.f)) * nv.x * sc;
        xn.y = xv.y + ((xv.y>0.f)?1.f:((xv.y<0.f)?-1.f:0.f)) * nv.y * sc;
        xn.z = xv.z + ((xv.z>0.f)?1.f:((xv.z<0.f)?-1.f:0.f)) * nv.z * sc;
        xn.w = xv.w + ((xv.w>0.f)?1.f:((xv.w<0.f)?-1.f:0.f)) * nv.w * sc;
        uint32_t* himg = (uint32_t*)g_x2;
        int c8 = lane >> 1, half = (lane & 1) << 3;
        uint32_t offc = (uint32_t)i*64u      + (((uint32_t)(c8 ^ (i      & 7)) << 4) + half)/4u;
        uint32_t offn = (uint32_t)(NN+i)*64u + (((uint32_t)(c8 ^ ((NN+i) & 7)) << 4) + half)/4u;
        *(uint2*)(himg + offc) = make_uint2(pack_h2(xv.x, xv.y), pack_h2(xv.z, xv.w));
        *(uint2*)(himg + offn) = make_uint2(pack_h2(xn.x, xn.y), pack_h2(xn.z, xn.w));
    } else if (blockIdx.x < NOISE_BLOCKS + WCONV_BLOCKS) {
        int id = (blockIdx.x - NOISE_BLOCKS)*blockDim.x + threadIdx.x;
        wconv_item(id, Wl0, Wr0, Wl1, Wr1, Wl2, Wr2);
    } else {
        int id = (blockIdx.x - NOISE_BLOCKS - WCONV_BLOCKS)*blockDim.x + threadIdx.x;
        if (id < NN) g_deg[id] = 0;
        if (id < 64) g_bsum[id] = 0;
    }
}

// ---------------- CSR build (proven 3-kernel scan) ----------------
__global__ void k_hist(const int* __restrict__ ei) {
    int e = blockIdx.x*blockDim.x + threadIdx.x;
    if (e < NE) atomicAdd(&g_deg[ei[NE + e]], 1);
}
__global__ void k_scan1() {
    __shared__ int ws[32];
    int tid = threadIdx.x, lane = tid & 31, w = tid >> 5;
    int gid = blockIdx.x*1024 + tid;
    int s = (gid < NN) ? g_deg[gid] : 0;
    #pragma unroll
    for (int o = 1; o < 32; o <<= 1) {
        int t = __shfl_up_sync(0xffffffffu, s, o);
        if (lane >= o) s += t;
    }
    if (lane == 31) ws[w] = s;
    __syncthreads();
    if (w == 0) {
        int x = ws[lane];
        #pragma unroll
        for (int o = 1; o < 32; o <<= 1) {
            int t = __shfl_up_sync(0xffffffffu, x, o);
            if (lane >= o) x += t;
        }
        ws[lane] = x;
    }
    __syncthreads();
    if (w > 0) s += ws[w-1];
    if (gid < NN) g_off[gid+1] = s;
    if (tid == 1023) g_bsum[blockIdx.x] = s;
}
__global__ void k_scan2() {
    __shared__ int s[64];
    int tid = threadIdx.x;
    int v = g_bsum[tid];
    s[tid] = v; __syncthreads();
    for (int o = 1; o < 64; o <<= 1) {
        int t = (tid >= o) ? s[tid-o] : 0;
        __syncthreads(); s[tid] += t; __syncthreads();
    }
    g_bsum[tid] = s[tid] - v;
}
__global__ void k_scan3() {
    int gid = blockIdx.x*1024 + threadIdx.x;
    if (gid >= NN) return;
    int incl = g_off[gid+1] + g_bsum[blockIdx.x];
    g_off[gid+1] = incl;
    g_pos[gid]   = incl - g_deg[gid];
    if (gid == 0) g_off[0] = 0;
}
__global__ void k_fill(const int* __restrict__ ei) {
    int e = blockIdx.x*blockDim.x + threadIdx.x;
    if (e < NE) {
        int dst = ei[NE + e];
        int p = atomicAdd(&g_pos[dst], 1);
        g_csr[p] = ei[e];
    }
}

// ---------------- 2-term fp16 GEMM: A*(Bh+Bl), 96KB smem, 2 CTA/SM ----------------
// smem: A fp16 [0,32K), Bh [32K,64K), Bl [64K,96K). cp.async raw-copy fills.
// A always from pre-swizzled fp16 image.
template<bool SPLIT47>
__global__ void __launch_bounds__(256, 2) k_gemm_mma(
    const uint8_t* __restrict__ Aimg,
    const uint8_t* __restrict__ imgHi, const uint8_t* __restrict__ imgLo,
    void* __restrict__ out0, float* __restrict__ out1, int M)
{
    extern __shared__ char smem[];
    const int tid = threadIdx.x;
    const int bm = blockIdx.x * 128;
    const int g  = blockIdx.y;
    uint32_t sb = smem_u32(smem);

    {
        const uint4* sa = (const uint4*)(Aimg + (size_t)bm*256);
        const uint4* bh = (const uint4*)(imgHi + (size_t)g*32768);
        const uint4* bl = (const uint4*)(imgLo + (size_t)g*32768);
        #pragma unroll
        for (int i = 0; i < 8; i++) {
            int id = tid + i*256;
            CP16(sb +          (uint32_t)id*16u, sa + id);
            CP16(sb + 32768u + (uint32_t)id*16u, bh + id);
            CP16(sb + 65536u + (uint32_t)id*16u, bl + id);
        }
        CP_COMMIT();
        CP_WAIT0();
    }
    __syncthreads();

    const int lane = tid & 31, w = tid >> 5;
    const int tm = (w >> 1) * 32, tn = (w & 1) * 64;
    const int lrow = lane & 15;
    const uint32_t lsel = (uint32_t)(lane >> 4);

    float acc[2][8][4];
    #pragma unroll
    for (int a = 0; a < 2; a++)
        #pragma unroll
        for (int b = 0; b < 8; b++)
            #pragma unroll
            for (int c = 0; c < 4; c++) acc[a][b][c] = 0.f;

    #pragma unroll
    for (int k16 = 0; k16 < 8; k16++) {
        const uint32_t c8 = (uint32_t)(k16*2) + lsel;
        uint32_t a[2][4];
        #pragma unroll
        for (int mt = 0; mt < 2; mt++) {
            int row = tm + mt*16 + lrow;
            ldsm4(a[mt], sb + (uint32_t)row*256u + ((c8 ^ (uint32_t)(row & 7)) << 4));
        }
        #pragma unroll
        for (int term = 0; term < 2; term++) {
            uint32_t bbase = sb + 32768u + (uint32_t)term*32768u;
            uint32_t b[4][4];
            #pragma unroll
            for (int bt = 0; bt < 4; bt++) {
                int n = tn + bt*16 + lrow;
                ldsm4(b[bt], bbase + (uint32_t)n*256u + ((c8 ^ (uint32_t)(n & 7)) << 4));
            }
            #pragma unroll
            for (int mt = 0; mt < 2; mt++)
                #pragma unroll
                for (int bt = 0; bt < 4; bt++) {
                    mma16816(acc[mt][bt*2+0], a[mt], b[bt][0], b[bt][2]);
                    mma16816(acc[mt][bt*2+1], a[mt], b[bt][1], b[bt][3]);
                }
        }
    }

    if constexpr (!SPLIT47) {
        if (g == 0) {   // t: packed fp16x2
            uint32_t* dst = (uint32_t*)out0;
            #pragma unroll
            for (int mt = 0; mt < 2; mt++) {
                int r0 = bm + tm + mt*16 + (lane >> 2);
                int r1 = r0 + 8;
                #pragma unroll
                for (int nt = 0; nt < 8; nt++) {
                    int cp = (tn + nt*8 + (lane & 3)*2) >> 1;
                    if (r0 < M) dst[(size_t)r0*64 + cp] = pack_h2(acc[mt][nt][0], acc[mt][nt][1]);
                    if (r1 < M) dst[(size_t)r1*64 + cp] = pack_h2(acc[mt][nt][2], acc[mt][nt][3]);
                }
            }
        } else {        // r: fp32
            #pragma unroll
            for (int mt = 0; mt < 2; mt++) {
                int r0 = bm + tm + mt*16 + (lane >> 2);
                int r1 = r0 + 8;
                #pragma unroll
                for (int nt = 0; nt < 8; nt++) {
                    int col = tn + nt*8 + (lane & 3)*2;
                    if (r0 < M) *(float2*)(out1 + (size_t)r0*128 + col)
                        = make_float2(acc[mt][nt][0], acc[mt][nt][1]);
                    if (r1 < M) *(float2*)(out1 + (size_t)r1*128 + col)
                        = make_float2(acc[mt][nt][2], acc[mt][nt][3]);
                }
            }
        }
    } else {
        float* dst = (w & 1) ? out1 : (float*)out0;
        #pragma unroll
        for (int mt = 0; mt < 2; mt++) {
            int r0 = bm + tm + mt*16 + (lane >> 2);
            int r1 = r0 + 8;
            #pragma unroll
            for (int nt = 0; nt < 8; nt++) {
                int cl = nt*8 + (lane & 3)*2;
                if (cl < DO) {
                    if (r0 < M) dst[(size_t)r0*DO + cl] = acc[mt][nt][0];
                    if (r1 < M) dst[(size_t)r1*DO + cl] = acc[mt][nt][2];
                }
                if (cl + 1 < DO) {
                    if (r0 < M) dst[(size_t)r0*DO + cl + 1] = acc[mt][nt][1];
                    if (r1 < M) dst[(size_t)r1*DO + cl + 1] = acc[mt][nt][3];
                }
            }
        }
    }
}

// ---------------- branch-merged 128-dim mean-agg + bias + self + relu ----------------
__global__ void k_agg128(const uint32_t* __restrict__ t, const float* __restrict__ r,
                         const float* __restrict__ bias,
                         uint32_t* __restrict__ himg, float* __restrict__ dout)
{
    int i = (blockIdx.x*blockDim.x + threadIdx.x) >> 5;
    int lane = threadIdx.x & 31;
    if (i >= NN) return;
    int e0 = g_off[i], e1 = g_off[i+1];
    float4 ac = make_float4(0.f,0.f,0.f,0.f);
    float4 an = make_float4(0.f,0.f,0.f,0.f);
    int e = e0;
    for (; e + 2 <= e1; e += 2) {
        int j0 = g_csr[e], j1 = g_csr[e+1];
        uint2 c0 = *(const uint2*)(t + ((size_t)j0        << 6) + (lane << 1));
        uint2 n0 = *(const uint2*)(t + ((size_t)(NN + j0) << 6) + (lane << 1));
        uint2 c1 = *(const uint2*)(t + ((size_t)j1        << 6) + (lane << 1));
        uint2 n1 = *(const uint2*)(t + ((size_t)(NN + j1) << 6) + (lane << 1));
        float2 cl0 = __half22float2(*(__half2*)&c0.x), ch0 = __half22float2(*(__half2*)&c0.y);
        float2 nl0 = __half22float2(*(__half2*)&n0.x), nh0 = __half22float2(*(__half2*)&n0.y);
        float2 cl1 = __half22float2(*(__half2*)&c1.x), ch1 = __half22float2(*(__half2*)&c1.y);
        float2 nl1 = __half22float2(*(__half2*)&n1.x), nh1 = __half22float2(*(__half2*)&n1.y);
        ac.x += cl0.x + cl1.x; ac.y += cl0.y + cl1.y;
        ac.z += ch0.x + ch1.x; ac.w += ch0.y + ch1.y;
        an.x += nl0.x + nl1.x; an.y += nl0.y + nl1.y;
        an.z += nh0.x + nh1.x; an.w += nh0.y + nh1.y;
    }
    if (e < e1) {
        int j = g_csr[e];
        uint2 c = *(const uint2*)(t + ((size_t)j        << 6) + (lane << 1));
        uint2 n = *(const uint2*)(t + ((size_t)(NN + j) << 6) + (lane << 1));
        float2 cl = __half22float2(*(__half2*)&c.x), ch = __half22float2(*(__half2*)&c.y);
        float2 nl = __half22float2(*(__half2*)&n.x), nh = __half22float2(*(__half2*)&n.y);
        ac.x += cl.x; ac.y += cl.y; ac.z += ch.x; ac.w += ch.y;
        an.x += nl.x; an.y += nl.y; an.z += nh.x; an.w += nh.y;
    }
    float inv = (e1 > e0) ? 1.f/(float)(e1 - e0) : 0.f;
    float4 bb = *(const float4*)(bias + (lane << 2));
    float4 rc = *(const float4*)(r + ((size_t)i        << 7) + (lane << 2));
    float4 rn = *(const float4*)(r + ((size_t)(NN + i) << 7) + (lane << 2));
    float4 oc, on;
    oc.x = fmaxf(fmaf(ac.x, inv, bb.x + rc.x), 0.f);
    oc.y = fmaxf(fmaf(ac.y, inv, bb.y + rc.y), 0.f);
    oc.z = fmaxf(fmaf(ac.z, inv, bb.z + rc.z), 0.f);
    oc.w = fmaxf(fmaf(ac.w, inv, bb.w + rc.w), 0.f);
    on.x = fmaxf(fmaf(an.x, inv, bb.x + rn.x), 0.f);
    on.y = fmaxf(fmaf(an.y, inv, bb.y + rn.y), 0.f);
    on.z = fmaxf(fmaf(an.z, inv, bb.z + rn.z), 0.f);
    on.w = fmaxf(fmaf(an.w, inv, bb.w + rn.w), 0.f);
    if (himg) {
        int c8 = lane >> 1, half = (lane & 1) << 3;
        uint32_t offc = (uint32_t)i*64u      + (((uint32_t)(c8 ^ (i      & 7)) << 4) + half)/4u;
        uint32_t offn = (uint32_t)(NN+i)*64u + (((uint32_t)(c8 ^ ((NN+i) & 7)) << 4) + half)/4u;
        *(uint2*)(himg + offc) = make_uint2(pack_h2(oc.x, oc.y), pack_h2(oc.z, oc.w));
        *(uint2*)(himg + offn) = make_uint2(pack_h2(on.x, on.y), pack_h2(on.z, on.w));
    }
    if (dout) {
        *(float4*)(dout + (size_t)i*DH + (lane << 2)) = oc;
        *(float4*)(dout + (size_t)OPB + (size_t)i*DH + (lane << 2)) = on;
    }
}

// ---------------- branch-merged 47-dim agg + log_softmax ----------------
__global__ void k_agg47(const float* __restrict__ t2, const float* __restrict__ r2,
                        const float* __restrict__ bias, float* __restrict__ dout)
{
    int i = (blockIdx.x*blockDim.x + threadIdx.x) >> 5;
    int lane = threadIdx.x & 31;
    if (i >= NN) return;
    int f0 = lane*2, f1 = lane*2 + 1;
    bool v0 = (f0 < DO), v1 = (f1 < DO);
    int e0 = g_off[i], e1 = g_off[i+1];
    float ac0 = 0.f, ac1 = 0.f, an0 = 0.f, an1 = 0.f;
    for (int e = e0; e < e1; e++) {
        int j = g_csr[e];
        const float* rowC = t2 + (size_t)j        * DO;
        const float* rowN = t2 + (size_t)(NN + j) * DO;
        if (v0) { ac0 += rowC[f0]; an0 += rowN[f0]; }
        if (v1) { ac1 += rowC[f1]; an1 += rowN[f1]; }
    }
    float inv = (e1 > e0) ? 1.f/(float)(e1 - e0) : 0.f;
    float b0 = v0 ? bias[f0] : 0.f;
    float b1 = v1 ? bias[f1] : 0.f;
    float zc0 = v0 ? fmaf(ac0, inv, b0 + r2[(size_t)i*DO + f0]) : -INFINITY;
    float zc1 = v1 ? fmaf(ac1, inv, b1 + r2[(size_t)i*DO + f1]) : -INFINITY;
    float zn0 = v0 ? fmaf(an0, inv, b0 + r2[(size_t)(NN+i)*DO + f0]) : -INFINITY;
    float zn1 = v1 ? fmaf(an1, inv, b1 + r2[(size_t)(NN+i)*DO + f1]) : -INFINITY;
    float mc = fmaxf(zc0, zc1), mn = fmaxf(zn0, zn1);
    #pragma unroll
    for (int o = 16; o; o >>= 1) {
        mc = fmaxf(mc, __shfl_xor_sync(0xffffffffu, mc, o));
        mn = fmaxf(mn, __shfl_xor_sync(0xffffffffu, mn, o));
    }
    float sc = (v0 ? expf(zc0 - mc) : 0.f) + (v1 ? expf(zc1 - mc) : 0.f);
    float sn = (v0 ? expf(zn0 - mn) : 0.f) + (v1 ? expf(zn1 - mn) : 0.f);
    #pragma unroll
    for (int o = 16; o; o >>= 1) {
        sc += __shfl_xor_sync(0xffffffffu, sc, o);
        sn += __shfl_xor_sync(0xffffffffu, sn, o);
    }
    float lc = mc + logf(sc), ln = mn + logf(sn);
    float* ycb = dout + (size_t)NN*DH                       + (size_t)i*DO;
    float* zcb = dout + (size_t)NN*(DH + DO)                + (size_t)i*DO;
    float* ynb = dout + (size_t)OPB + (size_t)NN*DH         + (size_t)i*DO;
    float* znb = dout + (size_t)OPB + (size_t)NN*(DH + DO)  + (size_t)i*DO;
    if (v0) { zcb[f0] = zc0; ycb[f0] = zc0 - lc; znb[f0] = zn0; ynb[f0] = zn0 - ln; }
    if (v1) { zcb[f1] = zc1; ycb[f1] = zc1 - lc; znb[f1] = zn1; ynb[f1] = zn1 - ln; }
}

// ---------------- orchestration ----------------
extern "C" void kernel_launch(void* const* d_in, const int* in_sizes, int n_in,
                              void* d_out, int out_size)
{
    const float* x     = (const float*)d_in[0];
    const int*   ei    = (const int*)  d_in[1];
    const float* noise = (const float*)d_in[2];
    const float* Wl0   = (const float*)d_in[3];
    const float* bl0   = (const float*)d_in[4];
    const float* Wr0   = (const float*)d_in[5];
    const float* Wl1   = (const float*)d_in[6];
    const float* bl1   = (const float*)d_in[7];
    const float* Wr1   = (const float*)d_in[8];
    const float* Wl2   = (const float*)d_in[9];
    const float* bl2   = (const float*)d_in[10];
    const float* Wr2   = (const float*)d_in[11];
    float* out = (float*)d_out;

    float *px2, *pt, *pr, *ph, *pt2, *pr2;
    uint8_t* pw;
    cudaGetSymbolAddress((void**)&px2, g_x2);
    cudaGetSymbolAddress((void**)&pt,  g_t);
    cudaGetSymbolAddress((void**)&pr,  g_r);
    cudaGetSymbolAddress((void**)&ph,  g_h);
    cudaGetSymbolAddress((void**)&pt2, g_t2);
    cudaGetSymbolAddress((void**)&pr2, g_r2);
    cudaGetSymbolAddress((void**)&pw,  g_wimg);

    const int SM = 98304;   // 96KB -> 2 CTAs/SM (measured-best config)
    cudaFuncSetAttribute((const void*)k_gemm_mma<false>, cudaFuncAttributeMaxDynamicSharedMemorySize, SM);
    cudaFuncSetAttribute((const void*)k_gemm_mma<true>,  cudaFuncAttributeMaxDynamicSharedMemorySize, SM);

    int gBlocks = (MM + 127)/128;
    dim3 gBig(gBlocks, 2);
    dim3 gSml(gBlocks, 1);
    int aggBlocks = (NN*32 + 255)/256;

    // idx 0: noise->x2 fp16 image + wconv + zero
    k_prep<<<NOISE_BLOCKS + WCONV_BLOCKS + ZERO_BLOCKS, 256>>>(
        x, noise, Wl0, Wr0, Wl1, Wr1, Wl2, Wr2);
    // idx 1-2: histogram + scan1
    k_hist <<<(NE + 255)/256, 256>>>(ei);
    k_scan1<<<NB_SCAN, 1024>>>();
    // idx 3: layer-0 GEMM (ncu capture target; A from x2 image)
    k_gemm_mma<false><<<gBig, 256, SM>>>((const uint8_t*)px2,
                                         pw, pw + 65536, pt, pr, MM);
    // idx 4-6: finish CSR
    k_scan2<<<1, 64>>>();
    k_scan3<<<NB_SCAN, 1024>>>();
    k_fill <<<(NE + 255)/256, 256>>>(ei);
    // layer 0 agg -> h1 fp16 image (g_h)
    k_agg128<<<aggBlocks, 256>>>((const uint32_t*)pt, pr, bl0, (uint32_t*)ph, nullptr);
    // layer 1 (A from h1 image); agg writes d_out fp32 + h2 fp16 image (g_x2)
    k_gemm_mma<false><<<gBig, 256, SM>>>((const uint8_t*)ph,
                                         pw + 131072, pw + 196608, pt, pr, MM);
    k_agg128<<<aggBlocks, 256>>>((const uint32_t*)pt, pr, bl1, (uint32_t*)px2, out);
    // layer 2 (A from h2 image)
    k_gemm_mma<true><<<gSml, 256, SM>>>((const uint8_t*)px2,
                                        pw + 262144, pw + 294912, pt2, pr2, MM);
    k_agg47<<<aggBlocks, 256>>>(pt2, pr2, bl2, out);
}

// round 15
// speedup vs baseline: 1.1821x; 1.0183x over previous
#include <cuda_runtime.h>
#include <cuda_bf16.h>
#include <cuda_fp16.h>
#include <math.h>
#include <stdint.h>

#define NN 50000
#define NE 800000
#define DH 128
#define DO 47
#define MM (2*NN)
#define OPB (NN*(DH+DO+DO))
#define NB_SCAN ((NN + 1023)/1024)

// ---------------- scratch ----------------
__device__ float g_x2[MM*DH];     // x2 fp16 image; later reused as h2 fp16 image
__device__ float g_t [MM*DH];     // t as fp16x2 (MM x 64 u32)
__device__ float g_r [MM*DH];     // r: fp16x2 (layer0) or fp32 (layer1)
__device__ float g_h [MM*DH];     // h1 fp16 image
__device__ float g_t2[MM*DO];
__device__ float g_r2[MM*DO];
__device__ int   g_deg[NN];
__device__ int   g_off[NN+1];
__device__ int   g_pos[NN];
__device__ int   g_csr[NE];
__device__ int   g_bsum[64];
// fp16 weight images, [g-slice 32KB][n row 256B] chunk-swizzled
__device__ __align__(16) uint8_t g_wimg[2*65536 + 2*65536 + 2*32768];

// ---------------- helpers ----------------
__device__ __forceinline__ uint32_t smem_u32(const void* p) {
    uint32_t a;
    asm("{ .reg .u64 t; cvta.to.shared.u64 t, %1; cvt.u32.u64 %0, t; }" : "=r"(a) : "l"(p));
    return a;
}
__device__ __forceinline__ void ldsm4(uint32_t* r, uint32_t addr) {
    asm volatile("ldmatrix.sync.aligned.m8n8.x4.shared.b16 {%0,%1,%2,%3}, [%4];"
        : "=r"(r[0]), "=r"(r[1]), "=r"(r[2]), "=r"(r[3]) : "r"(addr));
}
__device__ __forceinline__ void mma16816(float* c, const uint32_t* a, uint32_t b0, uint32_t b1) {
    asm volatile("mma.sync.aligned.m16n8k16.row.col.f32.f16.f16.f32 "
        "{%0,%1,%2,%3}, {%4,%5,%6,%7}, {%8,%9}, {%0,%1,%2,%3};"
        : "+f"(c[0]), "+f"(c[1]), "+f"(c[2]), "+f"(c[3])
        : "r"(a[0]), "r"(a[1]), "r"(a[2]), "r"(a[3]), "r"(b0), "r"(b1));
}
__device__ __forceinline__ uint32_t pack_h2(float a, float b) {
    __half2 h = __floats2half2_rn(a, b);
    return *(uint32_t*)&h;
}
__device__ __forceinline__ void cvt_hilo16(const float* v, uint32_t* hp, uint32_t* lp) {
    #pragma unroll
    for (int p = 0; p < 4; p++) {
        __half2 h2 = __floats2half2_rn(v[2*p], v[2*p+1]);
        float l0 = v[2*p]   - __low2float(h2);
        float l1 = v[2*p+1] - __high2float(h2);
        __half2 l2 = __floats2half2_rn(l0, l1);
        hp[p] = *(uint32_t*)&h2;
        lp[p] = *(uint32_t*)&l2;
    }
}
#define CP16(sm, gp) asm volatile("cp.async.cg.shared.global [%0], [%1], 16;" :: "r"(sm), "l"(gp))
#define CP_COMMIT()  asm volatile("cp.async.commit_group;" ::: "memory")
#define CP_WAIT0()   asm volatile("cp.async.wait_group 0;" ::: "memory")

// ---------------- weight image writer: [g 32KB][n][256B] ----------------
__device__ __forceinline__ void wconv_item(int id,
        const float* Wl0, const float* Wr0, const float* Wl1, const float* Wr1,
        const float* Wl2, const float* Wr2) {
    const float* src = nullptr;
    uint8_t *imgHi, *imgLo;
    int row, c8;
    if (id < 4096) {
        row = id >> 4; c8 = id & 15;
        imgHi = g_wimg;          imgLo = g_wimg + 65536;
        src = (row < 128) ? (Wl0 + (size_t)row*128) : (Wr0 + (size_t)(row-128)*128);
    } else if (id < 8192) {
        id -= 4096; row = id >> 4; c8 = id & 15;
        imgHi = g_wimg + 131072; imgLo = g_wimg + 196608;
        src = (row < 128) ? (Wl1 + (size_t)row*128) : (Wr1 + (size_t)(row-128)*128);
    } else if (id < 10240) {
        id -= 8192; row = id >> 4; c8 = id & 15;
        imgHi = g_wimg + 262144; imgLo = g_wimg + 294912;
        if (row < 47)                     src = Wl2 + (size_t)row*128;
        else if (row >= 64 && row < 111)  src = Wr2 + (size_t)(row-64)*128;
        else                              src = nullptr;
    } else return;
    float v[8];
    #pragma unroll
    for (int j = 0; j < 8; j++) v[j] = src ? src[c8*8 + j] : 0.f;
    uint32_t hp[4], lp[4];
    cvt_hilo16(v, hp, lp);
    int gsl = row >> 7, n = row & 127;
    uint32_t off = (uint32_t)gsl*32768u + (uint32_t)n*256u
                 + (uint32_t)((c8 ^ (n & 7)) << 4);
    *(uint4*)(imgHi + off) = make_uint4(hp[0], hp[1], hp[2], hp[3]);
    *(uint4*)(imgLo + off) = make_uint4(lp[0], lp[1], lp[2], lp[3]);
}

// ---------------- prep: noise->fp16 image + wconv + hist fused ----------------
// (g_deg zeroed by cudaMemsetAsync before this launch)
#define NOISE_BLOCKS (NN/8)
#define WCONV_BLOCKS 40
#define HIST_BLOCKS ((NE + 255)/256)
__global__ void k_prep(const float* __restrict__ x, const float* __restrict__ noise,
                       const int* __restrict__ ei,
                       const float* Wl0, const float* Wr0,
                       const float* Wl1, const float* Wr1,
                       const float* Wl2, const float* Wr2) {
    if (blockIdx.x < NOISE_BLOCKS) {
        int i = (blockIdx.x*blockDim.x + threadIdx.x) >> 5;
        int lane = threadIdx.x & 31;
        const float4 nv = *(const float4*)(noise + (size_t)i*DH + lane*4);
        float ss = nv.x*nv.x + nv.y*nv.y + nv.z*nv.z + nv.w*nv.w;
        #pragma unroll
        for (int o = 16; o; o >>= 1) ss += __shfl_xor_sync(0xffffffffu, ss, o);
        float sc = 0.1f / fmaxf(sqrtf(ss), 1e-12f);
        float4 xv = *(const float4*)(x + (size_t)i*DH + lane*4);
        float4 xn;
        xn.x = xv.x + ((xv.x>0.f)?1.f:((xv.x<0.f)?-1.f:0.f)) * nv.x * sc;
        xn.y = xv.y + ((xv.y>0.f)?1.f:((xv.y<0.f)?-1.f:0.f)) * nv.y * sc;
        xn.z = xv.z + ((xv.z>0.f)?1.f:((xv.z<0.f)?-1.f:0.f)) * nv.z * sc;
        xn.w = xv.w + ((xv.w>0.f)?1.f:((xv.w<0.f)?-1.f:0.f)) * nv.w * sc;
        uint32_t* himg = (uint32_t*)g_x2;
        int c8 = lane >> 1, half = (lane & 1) << 3;
        uint32_t offc = (uint32_t)i*64u      + (((uint32_t)(c8 ^ (i      & 7)) << 4) + half)/4u;
        uint32_t offn = (uint32_t)(NN+i)*64u + (((uint32_t)(c8 ^ ((NN+i) & 7)) << 4) + half)/4u;
        *(uint2*)(himg + offc) = make_uint2(pack_h2(xv.x, xv.y), pack_h2(xv.z, xv.w));
        *(uint2*)(himg + offn) = make_uint2(pack_h2(xn.x, xn.y), pack_h2(xn.z, xn.w));
    } else if (blockIdx.x < NOISE_BLOCKS + WCONV_BLOCKS) {
        int id = (blockIdx.x - NOISE_BLOCKS)*blockDim.x + threadIdx.x;
        wconv_item(id, Wl0, Wr0, Wl1, Wr1, Wl2, Wr2);
    } else {
        int e = (blockIdx.x - NOISE_BLOCKS - WCONV_BLOCKS)*blockDim.x + threadIdx.x;
        if (e < NE) atomicAdd(&g_deg[ei[NE + e]], 1);
    }
}

// ---------------- CSR scans ----------------
__global__ void k_scan1() {
    __shared__ int ws[32];
    int tid = threadIdx.x, lane = tid & 31, w = tid >> 5;
    int gid = blockIdx.x*1024 + tid;
    int s = (gid < NN) ? g_deg[gid] : 0;
    #pragma unroll
    for (int o = 1; o < 32; o <<= 1) {
        int t = __shfl_up_sync(0xffffffffu, s, o);
        if (lane >= o) s += t;
    }
    if (lane == 31) ws[w] = s;
    __syncthreads();
    if (w == 0) {
        int x = ws[lane];
        #pragma unroll
        for (int o = 1; o < 32; o <<= 1) {
            int t = __shfl_up_sync(0xffffffffu, x, o);
            if (lane >= o) x += t;
        }
        ws[lane] = x;
    }
    __syncthreads();
    if (w > 0) s += ws[w-1];
    if (gid < NN) g_off[gid+1] = s;
    if (tid == 1023) g_bsum[blockIdx.x] = s;
}
// merged scan2+scan3: every block redundantly scans the 49 block sums (no flags)
__global__ void k_scan23() {
    __shared__ int sS[64];
    int tid = threadIdx.x;
    if (tid < 64) {
        int lane = tid & 31;
        int v = (tid < NB_SCAN) ? g_bsum[tid] : 0;
        int s = v;
        #pragma unroll
        for (int o = 1; o < 32; o <<= 1) {
            int t = __shfl_up_sync(0xffffffffu, s, o);
            if (lane >= o) s += t;
        }
        sS[tid] = s;
    }
    __syncthreads();
    if (tid >= 32 && tid < 64) sS[tid] += sS[31];
    __syncthreads();
    int sprefix = (blockIdx.x == 0) ? 0 : sS[blockIdx.x - 1];
    int gid = blockIdx.x*1024 + tid;
    if (gid < NN) {
        int incl = g_off[gid+1] + sprefix;
        g_off[gid+1] = incl;
        g_pos[gid]   = incl - g_deg[gid];
    }
    if (gid == 0) g_off[0] = 0;
}
__global__ void k_fill(const int* __restrict__ ei) {
    int e = blockIdx.x*blockDim.x + threadIdx.x;
    if (e < NE) {
        int dst = ei[NE + e];
        int p = atomicAdd(&g_pos[dst], 1);
        g_csr[p] = ei[e];
    }
}

// ---------------- 2-term fp16 GEMM: A*(Bh+Bl), 96KB smem, 2 CTA/SM ----------------
// R16 (only with !SPLIT47): g==1 writes out1 as packed fp16x2 (stride 64 u32).
template<bool SPLIT47, bool R16>
__global__ void __launch_bounds__(256, 2) k_gemm_mma(
    const uint8_t* __restrict__ Aimg,
    const uint8_t* __restrict__ imgHi, const uint8_t* __restrict__ imgLo,
    void* __restrict__ out0, void* __restrict__ out1, int M)
{
    extern __shared__ char smem[];
    const int tid = threadIdx.x;
    const int bm = blockIdx.x * 128;
    const int g  = blockIdx.y;
    uint32_t sb = smem_u32(smem);

    {
        const uint4* sa = (const uint4*)(Aimg + (size_t)bm*256);
        const uint4* bh = (const uint4*)(imgHi + (size_t)g*32768);
        const uint4* bl = (const uint4*)(imgLo + (size_t)g*32768);
        #pragma unroll
        for (int i = 0; i < 8; i++) {
            int id = tid + i*256;
            CP16(sb +          (uint32_t)id*16u, sa + id);
            CP16(sb + 32768u + (uint32_t)id*16u, bh + id);
            CP16(sb + 65536u + (uint32_t)id*16u, bl + id);
        }
        CP_COMMIT();
        CP_WAIT0();
    }
    __syncthreads();

    const int lane = tid & 31, w = tid >> 5;
    const int tm = (w >> 1) * 32, tn = (w & 1) * 64;
    const int lrow = lane & 15;
    const uint32_t lsel = (uint32_t)(lane >> 4);

    float acc[2][8][4];
    #pragma unroll
    for (int a = 0; a < 2; a++)
        #pragma unroll
        for (int b = 0; b < 8; b++)
            #pragma unroll
            for (int c = 0; c < 4; c++) acc[a][b][c] = 0.f;

    #pragma unroll
    for (int k16 = 0; k16 < 8; k16++) {
        const uint32_t c8 = (uint32_t)(k16*2) + lsel;
        uint32_t a[2][4];
        #pragma unroll
        for (int mt = 0; mt < 2; mt++) {
            int row = tm + mt*16 + lrow;
            ldsm4(a[mt], sb + (uint32_t)row*256u + ((c8 ^ (uint32_t)(row & 7)) << 4));
        }
        #pragma unroll
        for (int term = 0; term < 2; term++) {
            uint32_t bbase = sb + 32768u + (uint32_t)term*32768u;
            uint32_t b[4][4];
            #pragma unroll
            for (int bt = 0; bt < 4; bt++) {
                int n = tn + bt*16 + lrow;
                ldsm4(b[bt], bbase + (uint32_t)n*256u + ((c8 ^ (uint32_t)(n & 7)) << 4));
            }
            #pragma unroll
            for (int mt = 0; mt < 2; mt++)
                #pragma unroll
                for (int bt = 0; bt < 4; bt++) {
                    mma16816(acc[mt][bt*2+0], a[mt], b[bt][0], b[bt][2]);
                    mma16816(acc[mt][bt*2+1], a[mt], b[bt][1], b[bt][3]);
                }
        }
    }

    if constexpr (!SPLIT47) {
        if (g == 0) {   // t: packed fp16x2
            uint32_t* dst = (uint32_t*)out0;
            #pragma unroll
            for (int mt = 0; mt < 2; mt++) {
                int r0 = bm + tm + mt*16 + (lane >> 2);
                int r1 = r0 + 8;
                #pragma unroll
                for (int nt = 0; nt < 8; nt++) {
                    int cp = (tn + nt*8 + (lane & 3)*2) >> 1;
                    if (r0 < M) dst[(size_t)r0*64 + cp] = pack_h2(acc[mt][nt][0], acc[mt][nt][1]);
                    if (r1 < M) dst[(size_t)r1*64 + cp] = pack_h2(acc[mt][nt][2], acc[mt][nt][3]);
                }
            }
        } else if constexpr (R16) {   // r: packed fp16x2 (stride 64 u32)
            uint32_t* dst = (uint32_t*)out1;
            #pragma unroll
            for (int mt = 0; mt < 2; mt++) {
                int r0 = bm + tm + mt*16 + (lane >> 2);
                int r1 = r0 + 8;
                #pragma unroll
                for (int nt = 0; nt < 8; nt++) {
                    int cp = (tn + nt*8 + (lane & 3)*2) >> 1;
                    if (r0 < M) dst[(size_t)r0*64 + cp] = pack_h2(acc[mt][nt][0], acc[mt][nt][1]);
                    if (r1 < M) dst[(size_t)r1*64 + cp] = pack_h2(acc[mt][nt][2], acc[mt][nt][3]);
                }
            }
        } else {        // r: fp32, stride 128
            float* dst = (float*)out1;
            #pragma unroll
            for (int mt = 0; mt < 2; mt++) {
                int r0 = bm + tm + mt*16 + (lane >> 2);
                int r1 = r0 + 8;
                #pragma unroll
                for (int nt = 0; nt < 8; nt++) {
                    int col = tn + nt*8 + (lane & 3)*2;
                    if (r0 < M) *(float2*)(dst + (size_t)r0*128 + col)
                        = make_float2(acc[mt][nt][0], acc[mt][nt][1]);
                    if (r1 < M) *(float2*)(dst + (size_t)r1*128 + col)
                        = make_float2(acc[mt][nt][2], acc[mt][nt][3]);
                }
            }
        }
    } else {
        float* dst = (w & 1) ? (float*)out1 : (float*)out0;
        #pragma unroll
        for (int mt = 0; mt < 2; mt++) {
            int r0 = bm + tm + mt*16 + (lane >> 2);
            int r1 = r0 + 8;
            #pragma unroll
            for (int nt = 0; nt < 8; nt++) {
                int cl = nt*8 + (lane & 3)*2;
                if (cl < DO) {
                    if (r0 < M) dst[(size_t)r0*DO + cl] = acc[mt][nt][0];
                    if (r1 < M) dst[(size_t)r1*DO + cl] = acc[mt][nt][2];
                }
                if (cl + 1 < DO) {
                    if (r0 < M) dst[(size_t)r0*DO + cl + 1] = acc[mt][nt][1];
                    if (r1 < M) dst[(size_t)r1*DO + cl + 1] = acc[mt][nt][3];
                }
            }
        }
    }
}

// ---------------- branch-merged 128-dim mean-agg + bias + self + relu ----------------
// r16: r stored as packed fp16x2 (stride 64 u32) instead of fp32 (stride 128).
__global__ void k_agg128(const uint32_t* __restrict__ t, const void* __restrict__ r,
                         int r16, const float* __restrict__ bias,
                         uint32_t* __restrict__ himg, float* __restrict__ dout)
{
    int i = (blockIdx.x*blockDim.x + threadIdx.x) >> 5;
    int lane = threadIdx.x & 31;
    if (i >= NN) return;
    int e0 = g_off[i], e1 = g_off[i+1];
    float4 ac = make_float4(0.f,0.f,0.f,0.f);
    float4 an = make_float4(0.f,0.f,0.f,0.f);
    int e = e0;
    for (; e + 2 <= e1; e += 2) {
        int j0 = g_csr[e], j1 = g_csr[e+1];
        uint2 c0 = *(const uint2*)(t + ((size_t)j0        << 6) + (lane << 1));
        uint2 n0 = *(const uint2*)(t + ((size_t)(NN + j0) << 6) + (lane << 1));
        uint2 c1 = *(const uint2*)(t + ((size_t)j1        << 6) + (lane << 1));
        uint2 n1 = *(const uint2*)(t + ((size_t)(NN + j1) << 6) + (lane << 1));
        float2 cl0 = __half22float2(*(__half2*)&c0.x), ch0 = __half22float2(*(__half2*)&c0.y);
        float2 nl0 = __half22float2(*(__half2*)&n0.x), nh0 = __half22float2(*(__half2*)&n0.y);
        float2 cl1 = __half22float2(*(__half2*)&c1.x), ch1 = __half22float2(*(__half2*)&c1.y);
        float2 nl1 = __half22float2(*(__half2*)&n1.x), nh1 = __half22float2(*(__half2*)&n1.y);
        ac.x += cl0.x + cl1.x; ac.y += cl0.y + cl1.y;
        ac.z += ch0.x + ch1.x; ac.w += ch0.y + ch1.y;
        an.x += nl0.x + nl1.x; an.y += nl0.y + nl1.y;
        an.z += nh0.x + nh1.x; an.w += nh0.y + nh1.y;
    }
    if (e < e1) {
        int j = g_csr[e];
        uint2 c = *(const uint2*)(t + ((size_t)j        << 6) + (lane << 1));
        uint2 n = *(const uint2*)(t + ((size_t)(NN + j) << 6) + (lane << 1));
        float2 cl = __half22float2(*(__half2*)&c.x), ch = __half22float2(*(__half2*)&c.y);
        float2 nl = __half22float2(*(__half2*)&n.x), nh = __half22float2(*(__half2*)&n.y);
        ac.x += cl.x; ac.y += cl.y; ac.z += ch.x; ac.w += ch.y;
        an.x += nl.x; an.y += nl.y; an.z += nh.x; an.w += nh.y;
    }
    float inv = (e1 > e0) ? 1.f/(float)(e1 - e0) : 0.f;
    float4 bb = *(const float4*)(bias + (lane << 2));
    float4 rc, rn;
    if (r16) {
        const uint32_t* rr = (const uint32_t*)r;
        uint2 uc = *(const uint2*)(rr + ((size_t)i        << 6) + (lane << 1));
        uint2 un = *(const uint2*)(rr + ((size_t)(NN + i) << 6) + (lane << 1));
        float2 a = __half22float2(*(__half2*)&uc.x), b = __half22float2(*(__half2*)&uc.y);
        rc = make_float4(a.x, a.y, b.x, b.y);
        a = __half22float2(*(__half2*)&un.x); b = __half22float2(*(__half2*)&un.y);
        rn = make_float4(a.x, a.y, b.x, b.y);
    } else {
        const float* rf = (const float*)r;
        rc = *(const float4*)(rf + ((size_t)i        << 7) + (lane << 2));
        rn = *(const float4*)(rf + ((size_t)(NN + i) << 7) + (lane << 2));
    }
    float4 oc, on;
    oc.x = fmaxf(fmaf(ac.x, inv, bb.x + rc.x), 0.f);
    oc.y = fmaxf(fmaf(ac.y, inv, bb.y + rc.y), 0.f);
    oc.z = fmaxf(fmaf(ac.z, inv, bb.z + rc.z), 0.f);
    oc.w = fmaxf(fmaf(ac.w, inv, bb.w + rc.w), 0.f);
    on.x = fmaxf(fmaf(an.x, inv, bb.x + rn.x), 0.f);
    on.y = fmaxf(fmaf(an.y, inv, bb.y + rn.y), 0.f);
    on.z = fmaxf(fmaf(an.z, inv, bb.z + rn.z), 0.f);
    on.w = fmaxf(fmaf(an.w, inv, bb.w + rn.w), 0.f);
    if (himg) {
        int c8 = lane >> 1, half = (lane & 1) << 3;
        uint32_t offc = (uint32_t)i*64u      + (((uint32_t)(c8 ^ (i      & 7)) << 4) + half)/4u;
        uint32_t offn = (uint32_t)(NN+i)*64u + (((uint32_t)(c8 ^ ((NN+i) & 7)) << 4) + half)/4u;
        *(uint2*)(himg + offc) = make_uint2(pack_h2(oc.x, oc.y), pack_h2(oc.z, oc.w));
        *(uint2*)(himg + offn) = make_uint2(pack_h2(on.x, on.y), pack_h2(on.z, on.w));
    }
    if (dout) {
        *(float4*)(dout + (size_t)i*DH + (lane << 2)) = oc;
        *(float4*)(dout + (size_t)OPB + (size_t)i*DH + (lane << 2)) = on;
    }
}

// ---------------- branch-merged 47-dim agg + log_softmax ----------------
__global__ void k_agg47(const float* __restrict__ t2, const float* __restrict__ r2,
                        const float* __restrict__ bias, float* __restrict__ dout)
{
    int i = (blockIdx.x*blockDim.x + threadIdx.x) >> 5;
    int lane = threadIdx.x & 31;
    if (i >= NN) return;
    int f0 = lane*2, f1 = lane*2 + 1;
    bool v0 = (f0 < DO), v1 = (f1 < DO);
    int e0 = g_off[i], e1 = g_off[i+1];
    float ac0 = 0.f, ac1 = 0.f, an0 = 0.f, an1 = 0.f;
    for (int e = e0; e < e1; e++) {
        int j = g_csr[e];
        const float* rowC = t2 + (size_t)j        * DO;
        const float* rowN = t2 + (size_t)(NN + j) * DO;
        if (v0) { ac0 += rowC[f0]; an0 += rowN[f0]; }
        if (v1) { ac1 += rowC[f1]; an1 += rowN[f1]; }
    }
    float inv = (e1 > e0) ? 1.f/(float)(e1 - e0) : 0.f;
    float b0 = v0 ? bias[f0] : 0.f;
    float b1 = v1 ? bias[f1] : 0.f;
    float zc0 = v0 ? fmaf(ac0, inv, b0 + r2[(size_t)i*DO + f0]) : -INFINITY;
    float zc1 = v1 ? fmaf(ac1, inv, b1 + r2[(size_t)i*DO + f1]) : -INFINITY;
    float zn0 = v0 ? fmaf(an0, inv, b0 + r2[(size_t)(NN+i)*DO + f0]) : -INFINITY;
    float zn1 = v1 ? fmaf(an1, inv, b1 + r2[(size_t)(NN+i)*DO + f1]) : -INFINITY;
    float mc = fmaxf(zc0, zc1), mn = fmaxf(zn0, zn1);
    #pragma unroll
    for (int o = 16; o; o >>= 1) {
        mc = fmaxf(mc, __shfl_xor_sync(0xffffffffu, mc, o));
        mn = fmaxf(mn, __shfl_xor_sync(0xffffffffu, mn, o));
    }
    float sc = (v0 ? expf(zc0 - mc) : 0.f) + (v1 ? expf(zc1 - mc) : 0.f);
    float sn = (v0 ? expf(zn0 - mn) : 0.f) + (v1 ? expf(zn1 - mn) : 0.f);
    #pragma unroll
    for (int o = 16; o; o >>= 1) {
        sc += __shfl_xor_sync(0xffffffffu, sc, o);
        sn += __shfl_xor_sync(0xffffffffu, sn, o);
    }
    float lc = mc + logf(sc), ln = mn + logf(sn);
    float* ycb = dout + (size_t)NN*DH                       + (size_t)i*DO;
    float* zcb = dout + (size_t)NN*(DH + DO)                + (size_t)i*DO;
    float* ynb = dout + (size_t)OPB + (size_t)NN*DH         + (size_t)i*DO;
    float* znb = dout + (size_t)OPB + (size_t)NN*(DH + DO)  + (size_t)i*DO;
    if (v0) { zcb[f0] = zc0; ycb[f0] = zc0 - lc; znb[f0] = zn0; ynb[f0] = zn0 - ln; }
    if (v1) { zcb[f1] = zc1; ycb[f1] = zc1 - lc; znb[f1] = zn1; ynb[f1] = zn1 - ln; }
}

// ---------------- orchestration ----------------
extern "C" void kernel_launch(void* const* d_in, const int* in_sizes, int n_in,
                              void* d_out, int out_size)
{
    const float* x     = (const float*)d_in[0];
    const int*   ei    = (const int*)  d_in[1];
    const float* noise = (const float*)d_in[2];
    const float* Wl0   = (const float*)d_in[3];
    const float* bl0   = (const float*)d_in[4];
    const float* Wr0   = (const float*)d_in[5];
    const float* Wl1   = (const float*)d_in[6];
    const float* bl1   = (const float*)d_in[7];
    const float* Wr1   = (const float*)d_in[8];
    const float* Wl2   = (const float*)d_in[9];
    const float* bl2   = (const float*)d_in[10];
    const float* Wr2   = (const float*)d_in[11];
    float* out = (float*)d_out;

    float *px2, *pt, *pr, *ph, *pt2, *pr2;
    int* pdeg;
    uint8_t* pw;
    cudaGetSymbolAddress((void**)&px2, g_x2);
    cudaGetSymbolAddress((void**)&pt,  g_t);
    cudaGetSymbolAddress((void**)&pr,  g_r);
    cudaGetSymbolAddress((void**)&ph,  g_h);
    cudaGetSymbolAddress((void**)&pt2, g_t2);
    cudaGetSymbolAddress((void**)&pr2, g_r2);
    cudaGetSymbolAddress((void**)&pdeg, g_deg);
    cudaGetSymbolAddress((void**)&pw,  g_wimg);

    const int SM = 98304;   // 96KB -> 2 CTAs/SM
    cudaFuncSetAttribute((const void*)k_gemm_mma<false,true>,  cudaFuncAttributeMaxDynamicSharedMemorySize, SM);
    cudaFuncSetAttribute((const void*)k_gemm_mma<false,false>, cudaFuncAttributeMaxDynamicSharedMemorySize, SM);
    cudaFuncSetAttribute((const void*)k_gemm_mma<true,false>,  cudaFuncAttributeMaxDynamicSharedMemorySize, SM);

    int gBlocks = (MM + 127)/128;
    dim3 gBig(gBlocks, 2);
    dim3 gSml(gBlocks, 1);
    int aggBlocks = (NN*32 + 255)/256;

    // node 0: zero degree counters (async memset, graph-capturable)
    cudaMemsetAsync(pdeg, 0, NN*sizeof(int));
    // node 1: noise->x2 fp16 image + wconv + hist (fused)
    k_prep<<<NOISE_BLOCKS + WCONV_BLOCKS + HIST_BLOCKS, 256>>>(
        x, noise, ei, Wl0, Wr0, Wl1, Wr1, Wl2, Wr2);
    // node 2: scan1
    k_scan1<<<NB_SCAN, 1024>>>();
    // node 3: layer-0 GEMM (A from x2 image; r written fp16)
    k_gemm_mma<false,true><<<gBig, 256, SM>>>((const uint8_t*)px2,
                                              pw, pw + 65536, pt, pr, MM);
    // node 4-5: scan23 + fill
    k_scan23<<<NB_SCAN, 1024>>>();
    k_fill<<<(NE + 255)/256, 256>>>(ei);
    // layer 0 agg (r fp16) -> h1 fp16 image (g_h)
    k_agg128<<<aggBlocks, 256>>>((const uint32_t*)pt, pr, 1, bl0, (uint32_t*)ph, nullptr);
    // layer 1 (A from h1 image; r fp32); agg writes d_out fp32 + h2 fp16 image (g_x2)
    k_gemm_mma<false,false><<<gBig, 256, SM>>>((const uint8_t*)ph,
                                               pw + 131072, pw + 196608, pt, pr, MM);
    k_agg128<<<aggBlocks, 256>>>((const uint32_t*)pt, pr, 0, bl1, (uint32_t*)px2, out);
    // layer 2 (A from h2 image)
    k_gemm_mma<true,false><<<gSml, 256, SM>>>((const uint8_t*)px2,
                                              pw + 262144, pw + 294912, pt2, pr2, MM);
    k_agg47<<<aggBlocks, 256>>>(pt2, pr2, bl2, out);
}

// round 16
// speedup vs baseline: 1.2795x; 1.0823x over previous
#include <cuda_runtime.h>
#include <cuda_bf16.h>
#include <cuda_fp16.h>
#include <math.h>
#include <stdint.h>

#define NN 50000
#define NE 800000
#define DH 128
#define DO 47
#define MM (2*NN)
#define OPB (NN*(DH+DO+DO))
#define NB_SCAN ((NN + 1023)/1024)
#define GB 782                    /* gemm blocks per g-slice */

// ---------------- scratch ----------------
__device__ float g_x2[MM*DH];     // x2 fp16 image; later reused as h2 fp16 image
__device__ float g_t [MM*DH];     // t as fp16x2 (MM x 64 u32)
__device__ float g_r [MM*DH];     // r: fp16x2 (layer0) or fp32 (layer1)
__device__ float g_h [MM*DH];     // h1 fp16 image
__device__ float g_t2[MM*DO];     // t2 as fp16x2 padded (MM x 24 u32)
__device__ float g_r2[MM*DO];     // r2 fp32 (stride DO)
__device__ int   g_deg[NN];
__device__ int   g_off[NN+1];
__device__ int   g_pos[NN];
__device__ int   g_csr[NE];
__device__ int   g_bsum[64];
// fp16 weight images, [g-slice 32KB][n row 256B] chunk-swizzled
__device__ __align__(16) uint8_t g_wimg[2*65536 + 2*65536 + 2*32768];

// ---------------- helpers ----------------
__device__ __forceinline__ uint32_t smem_u32(const void* p) {
    uint32_t a;
    asm("{ .reg .u64 t; cvta.to.shared.u64 t, %1; cvt.u32.u64 %0, t; }" : "=r"(a) : "l"(p));
    return a;
}
__device__ __forceinline__ void ldsm4(uint32_t* r, uint32_t addr) {
    asm volatile("ldmatrix.sync.aligned.m8n8.x4.shared.b16 {%0,%1,%2,%3}, [%4];"
        : "=r"(r[0]), "=r"(r[1]), "=r"(r[2]), "=r"(r[3]) : "r"(addr));
}
__device__ __forceinline__ void mma16816(float* c, const uint32_t* a, uint32_t b0, uint32_t b1) {
    asm volatile("mma.sync.aligned.m16n8k16.row.col.f32.f16.f16.f32 "
        "{%0,%1,%2,%3}, {%4,%5,%6,%7}, {%8,%9}, {%0,%1,%2,%3};"
        : "+f"(c[0]), "+f"(c[1]), "+f"(c[2]), "+f"(c[3])
        : "r"(a[0]), "r"(a[1]), "r"(a[2]), "r"(a[3]), "r"(b0), "r"(b1));
}
__device__ __forceinline__ uint32_t pack_h2(float a, float b) {
    __half2 h = __floats2half2_rn(a, b);
    return *(uint32_t*)&h;
}
__device__ __forceinline__ void cvt_hilo16(const float* v, uint32_t* hp, uint32_t* lp) {
    #pragma unroll
    for (int p = 0; p < 4; p++) {
        __half2 h2 = __floats2half2_rn(v[2*p], v[2*p+1]);
        float l0 = v[2*p]   - __low2float(h2);
        float l1 = v[2*p+1] - __high2float(h2);
        __half2 l2 = __floats2half2_rn(l0, l1);
        hp[p] = *(uint32_t*)&h2;
        lp[p] = *(uint32_t*)&l2;
    }
}
#define CP16(sm, gp) asm volatile("cp.async.cg.shared.global [%0], [%1], 16;" :: "r"(sm), "l"(gp))
#define CP_COMMIT()  asm volatile("cp.async.commit_group;" ::: "memory")
#define CP_WAIT0()   asm volatile("cp.async.wait_group 0;" ::: "memory")

// ---------------- weight image writer: [g 32KB][n][256B] ----------------
__device__ __forceinline__ void wconv_item(int id,
        const float* Wl0, const float* Wr0, const float* Wl1, const float* Wr1,
        const float* Wl2, const float* Wr2) {
    const float* src = nullptr;
    uint8_t *imgHi, *imgLo;
    int row, c8;
    if (id < 4096) {
        row = id >> 4; c8 = id & 15;
        imgHi = g_wimg;          imgLo = g_wimg + 65536;
        src = (row < 128) ? (Wl0 + (size_t)row*128) : (Wr0 + (size_t)(row-128)*128);
    } else if (id < 8192) {
        id -= 4096; row = id >> 4; c8 = id & 15;
        imgHi = g_wimg + 131072; imgLo = g_wimg + 196608;
        src = (row < 128) ? (Wl1 + (size_t)row*128) : (Wr1 + (size_t)(row-128)*128);
    } else if (id < 10240) {
        id -= 8192; row = id >> 4; c8 = id & 15;
        imgHi = g_wimg + 262144; imgLo = g_wimg + 294912;
        if (row < 47)                     src = Wl2 + (size_t)row*128;
        else if (row >= 64 && row < 111)  src = Wr2 + (size_t)(row-64)*128;
        else                              src = nullptr;
    } else return;
    float v[8];
    #pragma unroll
    for (int j = 0; j < 8; j++) v[j] = src ? src[c8*8 + j] : 0.f;
    uint32_t hp[4], lp[4];
    cvt_hilo16(v, hp, lp);
    int gsl = row >> 7, n = row & 127;
    uint32_t off = (uint32_t)gsl*32768u + (uint32_t)n*256u
                 + (uint32_t)((c8 ^ (n & 7)) << 4);
    *(uint4*)(imgHi + off) = make_uint4(hp[0], hp[1], hp[2], hp[3]);
    *(uint4*)(imgLo + off) = make_uint4(lp[0], lp[1], lp[2], lp[3]);
}

// ---------------- prep: noise->fp16 image + wconv + hist fused ----------------
#define NOISE_BLOCKS (NN/8)
#define WCONV_BLOCKS 40
#define HIST_BLOCKS ((NE + 255)/256)
__global__ void k_prep(const float* __restrict__ x, const float* __restrict__ noise,
                       const int* __restrict__ ei,
                       const float* Wl0, const float* Wr0,
                       const float* Wl1, const float* Wr1,
                       const float* Wl2, const float* Wr2) {
    if (blockIdx.x < NOISE_BLOCKS) {
        int i = (blockIdx.x*blockDim.x + threadIdx.x) >> 5;
        int lane = threadIdx.x & 31;
        const float4 nv = *(const float4*)(noise + (size_t)i*DH + lane*4);
        float ss = nv.x*nv.x + nv.y*nv.y + nv.z*nv.z + nv.w*nv.w;
        #pragma unroll
        for (int o = 16; o; o >>= 1) ss += __shfl_xor_sync(0xffffffffu, ss, o);
        float sc = 0.1f / fmaxf(sqrtf(ss), 1e-12f);
        float4 xv = *(const float4*)(x + (size_t)i*DH + lane*4);
        float4 xn;
        xn.x = xv.x + ((xv.x>0.f)?1.f:((xv.x<0.f)?-1.f:0.f)) * nv.x * sc;
        xn.y = xv.y + ((xv.y>0.f)?1.f:((xv.y<0.f)?-1.f:0.f)) * nv.y * sc;
        xn.z = xv.z + ((xv.z>0.f)?1.f:((xv.z<0.f)?-1.f:0.f)) * nv.z * sc;
        xn.w = xv.w + ((xv.w>0.f)?1.f:((xv.w<0.f)?-1.f:0.f)) * nv.w * sc;
        uint32_t* himg = (uint32_t*)g_x2;
        int c8 = lane >> 1, half = (lane & 1) << 3;
        uint32_t offc = (uint32_t)i*64u      + (((uint32_t)(c8 ^ (i      & 7)) << 4) + half)/4u;
        uint32_t offn = (uint32_t)(NN+i)*64u + (((uint32_t)(c8 ^ ((NN+i) & 7)) << 4) + half)/4u;
        *(uint2*)(himg + offc) = make_uint2(pack_h2(xv.x, xv.y), pack_h2(xv.z, xv.w));
        *(uint2*)(himg + offn) = make_uint2(pack_h2(xn.x, xn.y), pack_h2(xn.z, xn.w));
    } else if (blockIdx.x < NOISE_BLOCKS + WCONV_BLOCKS) {
        int id = (blockIdx.x - NOISE_BLOCKS)*blockDim.x + threadIdx.x;
        wconv_item(id, Wl0, Wr0, Wl1, Wr1, Wl2, Wr2);
    } else {
        int e = (blockIdx.x - NOISE_BLOCKS - WCONV_BLOCKS)*blockDim.x + threadIdx.x;
        if (e < NE) atomicAdd(&g_deg[ei[NE + e]], 1);
    }
}

// ---------------- CSR scans ----------------
__global__ void k_scan1() {
    __shared__ int ws[32];
    int tid = threadIdx.x, lane = tid & 31, w = tid >> 5;
    int gid = blockIdx.x*1024 + tid;
    int s = (gid < NN) ? g_deg[gid] : 0;
    #pragma unroll
    for (int o = 1; o < 32; o <<= 1) {
        int t = __shfl_up_sync(0xffffffffu, s, o);
        if (lane >= o) s += t;
    }
    if (lane == 31) ws[w] = s;
    __syncthreads();
    if (w == 0) {
        int x = ws[lane];
        #pragma unroll
        for (int o = 1; o < 32; o <<= 1) {
            int t = __shfl_up_sync(0xffffffffu, x, o);
            if (lane >= o) x += t;
        }
        ws[lane] = x;
    }
    __syncthreads();
    if (w > 0) s += ws[w-1];
    if (gid < NN) g_off[gid+1] = s;
    if (tid == 1023) g_bsum[blockIdx.x] = s;
}
__global__ void k_scan23() {
    __shared__ int sS[64];
    int tid = threadIdx.x;
    if (tid < 64) {
        int lane = tid & 31;
        int v = (tid < NB_SCAN) ? g_bsum[tid] : 0;
        int s = v;
        #pragma unroll
        for (int o = 1; o < 32; o <<= 1) {
            int t = __shfl_up_sync(0xffffffffu, s, o);
            if (lane >= o) s += t;
        }
        sS[tid] = s;
    }
    __syncthreads();
    if (tid >= 32 && tid < 64) sS[tid] += sS[31];
    __syncthreads();
    int sprefix = (blockIdx.x == 0) ? 0 : sS[blockIdx.x - 1];
    int gid = blockIdx.x*1024 + tid;
    if (gid < NN) {
        int incl = g_off[gid+1] + sprefix;
        g_off[gid+1] = incl;
        g_pos[gid]   = incl - g_deg[gid];
    }
    if (gid == 0) g_off[0] = 0;
}

// ---------------- 2-term fp16 GEMM: A*(Bh+Bl), 96KB smem, 2 CTA/SM ----------------
// FILL: blocks with blockIdx.y>=2 run the CSR fill instead (overlapped with GEMM).
// SPLIT47: cols 0-63 -> out0 fp16x2 packed (stride 24 u32), 64-127 -> out1 fp32 (stride DO)
// R16: g==1 writes out1 fp16x2 (stride 64 u32) instead of fp32 (stride 128).
template<bool SPLIT47, bool R16, bool FILL>
__global__ void __launch_bounds__(256, 2) k_gemm_mma(
    const uint8_t* __restrict__ Aimg,
    const uint8_t* __restrict__ imgHi, const uint8_t* __restrict__ imgLo,
    void* __restrict__ out0, void* __restrict__ out1, int M,
    const int* __restrict__ ei)
{
    extern __shared__ char smem[];
    const int tid = threadIdx.x;

    if constexpr (FILL) {
        if (blockIdx.y >= 2) {
            int e = ((blockIdx.y - 2)*GB + blockIdx.x)*256 + tid;
            if (e < NE) {
                int dst = ei[NE + e];
                int p = atomicAdd(&g_pos[dst], 1);
                g_csr[p] = ei[e];
            }
            return;
        }
    }

    const int bm = blockIdx.x * 128;
    const int g  = blockIdx.y;
    uint32_t sb = smem_u32(smem);

    {
        const uint4* sa = (const uint4*)(Aimg + (size_t)bm*256);
        const uint4* bh = (const uint4*)(imgHi + (size_t)g*32768);
        const uint4* bl = (const uint4*)(imgLo + (size_t)g*32768);
        #pragma unroll
        for (int i = 0; i < 8; i++) {
            int id = tid + i*256;
            CP16(sb +          (uint32_t)id*16u, sa + id);
            CP16(sb + 32768u + (uint32_t)id*16u, bh + id);
            CP16(sb + 65536u + (uint32_t)id*16u, bl + id);
        }
        CP_COMMIT();
        CP_WAIT0();
    }
    __syncthreads();

    const int lane = tid & 31, w = tid >> 5;
    const int tm = (w >> 1) * 32, tn = (w & 1) * 64;
    const int lrow = lane & 15;
    const uint32_t lsel = (uint32_t)(lane >> 4);

    float acc[2][8][4];
    #pragma unroll
    for (int a = 0; a < 2; a++)
        #pragma unroll
        for (int b = 0; b < 8; b++)
            #pragma unroll
            for (int c = 0; c < 4; c++) acc[a][b][c] = 0.f;

    #pragma unroll
    for (int k16 = 0; k16 < 8; k16++) {
        const uint32_t c8 = (uint32_t)(k16*2) + lsel;
        uint32_t a[2][4];
        #pragma unroll
        for (int mt = 0; mt < 2; mt++) {
            int row = tm + mt*16 + lrow;
            ldsm4(a[mt], sb + (uint32_t)row*256u + ((c8 ^ (uint32_t)(row & 7)) << 4));
        }
        #pragma unroll
        for (int term = 0; term < 2; term++) {
            uint32_t bbase = sb + 32768u + (uint32_t)term*32768u;
            uint32_t b[4][4];
            #pragma unroll
            for (int bt = 0; bt < 4; bt++) {
                int n = tn + bt*16 + lrow;
                ldsm4(b[bt], bbase + (uint32_t)n*256u + ((c8 ^ (uint32_t)(n & 7)) << 4));
            }
            #pragma unroll
            for (int mt = 0; mt < 2; mt++)
                #pragma unroll
                for (int bt = 0; bt < 4; bt++) {
                    mma16816(acc[mt][bt*2+0], a[mt], b[bt][0], b[bt][2]);
                    mma16816(acc[mt][bt*2+1], a[mt], b[bt][1], b[bt][3]);
                }
        }
    }

    if constexpr (!SPLIT47) {
        if (g == 0) {   // t: packed fp16x2
            uint32_t* dst = (uint32_t*)out0;
            #pragma unroll
            for (int mt = 0; mt < 2; mt++) {
                int r0 = bm + tm + mt*16 + (lane >> 2);
                int r1 = r0 + 8;
                #pragma unroll
                for (int nt = 0; nt < 8; nt++) {
                    int cp = (tn + nt*8 + (lane & 3)*2) >> 1;
                    if (r0 < M) dst[(size_t)r0*64 + cp] = pack_h2(acc[mt][nt][0], acc[mt][nt][1]);
                    if (r1 < M) dst[(size_t)r1*64 + cp] = pack_h2(acc[mt][nt][2], acc[mt][nt][3]);
                }
            }
        } else if constexpr (R16) {   // r: packed fp16x2 (stride 64 u32)
            uint32_t* dst = (uint32_t*)out1;
            #pragma unroll
            for (int mt = 0; mt < 2; mt++) {
                int r0 = bm + tm + mt*16 + (lane >> 2);
                int r1 = r0 + 8;
                #pragma unroll
                for (int nt = 0; nt < 8; nt++) {
                    int cp = (tn + nt*8 + (lane & 3)*2) >> 1;
                    if (r0 < M) dst[(size_t)r0*64 + cp] = pack_h2(acc[mt][nt][0], acc[mt][nt][1]);
                    if (r1 < M) dst[(size_t)r1*64 + cp] = pack_h2(acc[mt][nt][2], acc[mt][nt][3]);
                }
            }
        } else {        // r: fp32, stride 128
            float* dst = (float*)out1;
            #pragma unroll
            for (int mt = 0; mt < 2; mt++) {
                int r0 = bm + tm + mt*16 + (lane >> 2);
                int r1 = r0 + 8;
                #pragma unroll
                for (int nt = 0; nt < 8; nt++) {
                    int col = tn + nt*8 + (lane & 3)*2;
                    if (r0 < M) *(float2*)(dst + (size_t)r0*128 + col)
                        = make_float2(acc[mt][nt][0], acc[mt][nt][1]);
                    if (r1 < M) *(float2*)(dst + (size_t)r1*128 + col)
                        = make_float2(acc[mt][nt][2], acc[mt][nt][3]);
                }
            }
        }
    } else {
        if ((w & 1) == 0) {   // t2: packed fp16x2, stride 24 u32 (cols 0..46, col 47 pad=0)
            uint32_t* dst = (uint32_t*)out0;
            #pragma unroll
            for (int mt = 0; mt < 2; mt++) {
                int r0 = bm + tm + mt*16 + (lane >> 2);
                int r1 = r0 + 8;
                #pragma unroll
                for (int nt = 0; nt < 8; nt++) {
                    int cl = nt*8 + (lane & 3)*2;
                    if (cl < DO) {
                        int cp = cl >> 1;
                        if (r0 < M) dst[(size_t)r0*24 + cp] = pack_h2(acc[mt][nt][0], acc[mt][nt][1]);
                        if (r1 < M) dst[(size_t)r1*24 + cp] = pack_h2(acc[mt][nt][2], acc[mt][nt][3]);
                    }
                }
            }
        } else {              // r2: fp32, stride DO
            float* dst = (float*)out1;
            #pragma unroll
            for (int mt = 0; mt < 2; mt++) {
                int r0 = bm + tm + mt*16 + (lane >> 2);
                int r1 = r0 + 8;
                #pragma unroll
                for (int nt = 0; nt < 8; nt++) {
                    int cl = nt*8 + (lane & 3)*2;
                    if (cl < DO) {
                        if (r0 < M) dst[(size_t)r0*DO + cl] = acc[mt][nt][0];
                        if (r1 < M) dst[(size_t)r1*DO + cl] = acc[mt][nt][2];
                    }
                    if (cl + 1 < DO) {
                        if (r0 < M) dst[(size_t)r0*DO + cl + 1] = acc[mt][nt][1];
                        if (r1 < M) dst[(size_t)r1*DO + cl + 1] = acc[mt][nt][3];
                    }
                }
            }
        }
    }
}

// ---------------- branch-merged 128-dim mean-agg + bias + self + relu ----------------
__global__ void k_agg128(const uint32_t* __restrict__ t, const void* __restrict__ r,
                         int r16, const float* __restrict__ bias,
                         uint32_t* __restrict__ himg, float* __restrict__ dout)
{
    int i = (blockIdx.x*blockDim.x + threadIdx.x) >> 5;
    int lane = threadIdx.x & 31;
    if (i >= NN) return;
    int e0 = g_off[i], e1 = g_off[i+1];
    float4 ac = make_float4(0.f,0.f,0.f,0.f);
    float4 an = make_float4(0.f,0.f,0.f,0.f);
    int e = e0;
    for (; e + 2 <= e1; e += 2) {
        int j0 = g_csr[e], j1 = g_csr[e+1];
        uint2 c0 = *(const uint2*)(t + ((size_t)j0        << 6) + (lane << 1));
        uint2 n0 = *(const uint2*)(t + ((size_t)(NN + j0) << 6) + (lane << 1));
        uint2 c1 = *(const uint2*)(t + ((size_t)j1        << 6) + (lane << 1));
        uint2 n1 = *(const uint2*)(t + ((size_t)(NN + j1) << 6) + (lane << 1));
        float2 cl0 = __half22float2(*(__half2*)&c0.x), ch0 = __half22float2(*(__half2*)&c0.y);
        float2 nl0 = __half22float2(*(__half2*)&n0.x), nh0 = __half22float2(*(__half2*)&n0.y);
        float2 cl1 = __half22float2(*(__half2*)&c1.x), ch1 = __half22float2(*(__half2*)&c1.y);
        float2 nl1 = __half22float2(*(__half2*)&n1.x), nh1 = __half22float2(*(__half2*)&n1.y);
        ac.x += cl0.x + cl1.x; ac.y += cl0.y + cl1.y;
        ac.z += ch0.x + ch1.x; ac.w += ch0.y + ch1.y;
        an.x += nl0.x + nl1.x; an.y += nl0.y + nl1.y;
        an.z += nh0.x + nh1.x; an.w += nh0.y + nh1.y;
    }
    if (e < e1) {
        int j = g_csr[e];
        uint2 c = *(const uint2*)(t + ((size_t)j        << 6) + (lane << 1));
        uint2 n = *(const uint2*)(t + ((size_t)(NN + j) << 6) + (lane << 1));
        float2 cl = __half22float2(*(__half2*)&c.x), ch = __half22float2(*(__half2*)&c.y);
        float2 nl = __half22float2(*(__half2*)&n.x), nh = __half22float2(*(__half2*)&n.y);
        ac.x += cl.x; ac.y += cl.y; ac.z += ch.x; ac.w += ch.y;
        an.x += nl.x; an.y += nl.y; an.z += nh.x; an.w += nh.y;
    }
    float inv = (e1 > e0) ? 1.f/(float)(e1 - e0) : 0.f;
    float4 bb = *(const float4*)(bias + (lane << 2));
    float4 rc, rn;
    if (r16) {
        const uint32_t* rr = (const uint32_t*)r;
        uint2 uc = *(const uint2*)(rr + ((size_t)i        << 6) + (lane << 1));
        uint2 un = *(const uint2*)(rr + ((size_t)(NN + i) << 6) + (lane << 1));
        float2 a = __half22float2(*(__half2*)&uc.x), b = __half22float2(*(__half2*)&uc.y);
        rc = make_float4(a.x, a.y, b.x, b.y);
        a = __half22float2(*(__half2*)&un.x); b = __half22float2(*(__half2*)&un.y);
        rn = make_float4(a.x, a.y, b.x, b.y);
    } else {
        const float* rf = (const float*)r;
        rc = *(const float4*)(rf + ((size_t)i        << 7) + (lane << 2));
        rn = *(const float4*)(rf + ((size_t)(NN + i) << 7) + (lane << 2));
    }
    float4 oc, on;
    oc.x = fmaxf(fmaf(ac.x, inv, bb.x + rc.x), 0.f);
    oc.y = fmaxf(fmaf(ac.y, inv, bb.y + rc.y), 0.f);
    oc.z = fmaxf(fmaf(ac.z, inv, bb.z + rc.z), 0.f);
    oc.w = fmaxf(fmaf(ac.w, inv, bb.w + rc.w), 0.f);
    on.x = fmaxf(fmaf(an.x, inv, bb.x + rn.x), 0.f);
    on.y = fmaxf(fmaf(an.y, inv, bb.y + rn.y), 0.f);
    on.z = fmaxf(fmaf(an.z, inv, bb.z + rn.z), 0.f);
    on.w = fmaxf(fmaf(an.w, inv, bb.w + rn.w), 0.f);
    if (himg) {
        int c8 = lane >> 1, half = (lane & 1) << 3;
        uint32_t offc = (uint32_t)i*64u      + (((uint32_t)(c8 ^ (i      & 7)) << 4) + half)/4u;
        uint32_t offn = (uint32_t)(NN+i)*64u + (((uint32_t)(c8 ^ ((NN+i) & 7)) << 4) + half)/4u;
        *(uint2*)(himg + offc) = make_uint2(pack_h2(oc.x, oc.y), pack_h2(oc.z, oc.w));
        *(uint2*)(himg + offn) = make_uint2(pack_h2(on.x, on.y), pack_h2(on.z, on.w));
    }
    if (dout) {
        *(float4*)(dout + (size_t)i*DH + (lane << 2)) = oc;
        *(float4*)(dout + (size_t)OPB + (size_t)i*DH + (lane << 2)) = on;
    }
}

// ---------------- branch-merged 47-dim agg (fp16 t2) + log_softmax ----------------
__global__ void k_agg47(const uint32_t* __restrict__ t2u, const float* __restrict__ r2,
                        const float* __restrict__ bias, float* __restrict__ dout)
{
    int i = (blockIdx.x*blockDim.x + threadIdx.x) >> 5;
    int lane = threadIdx.x & 31;
    if (i >= NN) return;
    int f0 = lane*2, f1 = lane*2 + 1;
    bool lv = (lane < 24);
    bool v0 = (f0 < DO), v1 = (f1 < DO);
    int e0 = g_off[i], e1 = g_off[i+1];
    float ac0 = 0.f, ac1 = 0.f, an0 = 0.f, an1 = 0.f;
    for (int e = e0; e < e1; e++) {
        int j = g_csr[e];
        uint32_t uc = lv ? t2u[(size_t)j*24 + lane]        : 0u;
        uint32_t un = lv ? t2u[(size_t)(NN + j)*24 + lane] : 0u;
        float2 fc = __half22float2(*(__half2*)&uc);
        float2 fn = __half22float2(*(__half2*)&un);
        ac0 += fc.x; ac1 += fc.y;
        an0 += fn.x; an1 += fn.y;
    }
    float inv = (e1 > e0) ? 1.f/(float)(e1 - e0) : 0.f;
    float b0 = v0 ? bias[f0] : 0.f;
    float b1 = v1 ? bias[f1] : 0.f;
    float zc0 = v0 ? fmaf(ac0, inv, b0 + r2[(size_t)i*DO + f0]) : -INFINITY;
    float zc1 = v1 ? fmaf(ac1, inv, b1 + r2[(size_t)i*DO + f1]) : -INFINITY;
    float zn0 = v0 ? fmaf(an0, inv, b0 + r2[(size_t)(NN+i)*DO + f0]) : -INFINITY;
    float zn1 = v1 ? fmaf(an1, inv, b1 + r2[(size_t)(NN+i)*DO + f1]) : -INFINITY;
    float mc = fmaxf(zc0, zc1), mn = fmaxf(zn0, zn1);
    #pragma unroll
    for (int o = 16; o; o >>= 1) {
        mc = fmaxf(mc, __shfl_xor_sync(0xffffffffu, mc, o));
        mn = fmaxf(mn, __shfl_xor_sync(0xffffffffu, mn, o));
    }
    float sc = (v0 ? expf(zc0 - mc) : 0.f) + (v1 ? expf(zc1 - mc) : 0.f);
    float sn = (v0 ? expf(zn0 - mn) : 0.f) + (v1 ? expf(zn1 - mn) : 0.f);
    #pragma unroll
    for (int o = 16; o; o >>= 1) {
        sc += __shfl_xor_sync(0xffffffffu, sc, o);
        sn += __shfl_xor_sync(0xffffffffu, sn, o);
    }
    float lc = mc + logf(sc), ln = mn + logf(sn);
    float* ycb = dout + (size_t)NN*DH                       + (size_t)i*DO;
    float* zcb = dout + (size_t)NN*(DH + DO)                + (size_t)i*DO;
    float* ynb = dout + (size_t)OPB + (size_t)NN*DH         + (size_t)i*DO;
    float* znb = dout + (size_t)OPB + (size_t)NN*(DH + DO)  + (size_t)i*DO;
    if (v0) { zcb[f0] = zc0; ycb[f0] = zc0 - lc; znb[f0] = zn0; ynb[f0] = zn0 - ln; }
    if (v1) { zcb[f1] = zc1; ycb[f1] = zc1 - lc; znb[f1] = zn1; ynb[f1] = zn1 - ln; }
}

// ---------------- orchestration ----------------
extern "C" void kernel_launch(void* const* d_in, const int* in_sizes, int n_in,
                              void* d_out, int out_size)
{
    const float* x     = (const float*)d_in[0];
    const int*   ei    = (const int*)  d_in[1];
    const float* noise = (const float*)d_in[2];
    const float* Wl0   = (const float*)d_in[3];
    const float* bl0   = (const float*)d_in[4];
    const float* Wr0   = (const float*)d_in[5];
    const float* Wl1   = (const float*)d_in[6];
    const float* bl1   = (const float*)d_in[7];
    const float* Wr1   = (const float*)d_in[8];
    const float* Wl2   = (const float*)d_in[9];
    const float* bl2   = (const float*)d_in[10];
    const float* Wr2   = (const float*)d_in[11];
    float* out = (float*)d_out;

    float *px2, *pt, *pr, *ph, *pt2, *pr2;
    int* pdeg;
    uint8_t* pw;
    cudaGetSymbolAddress((void**)&px2, g_x2);
    cudaGetSymbolAddress((void**)&pt,  g_t);
    cudaGetSymbolAddress((void**)&pr,  g_r);
    cudaGetSymbolAddress((void**)&ph,  g_h);
    cudaGetSymbolAddress((void**)&pt2, g_t2);
    cudaGetSymbolAddress((void**)&pr2, g_r2);
    cudaGetSymbolAddress((void**)&pdeg, g_deg);
    cudaGetSymbolAddress((void**)&pw,  g_wimg);

    const int SM = 98304;   // 96KB -> 2 CTAs/SM
    cudaFuncSetAttribute((const void*)k_gemm_mma<false,true,true>,   cudaFuncAttributeMaxDynamicSharedMemorySize, SM);
    cudaFuncSetAttribute((const void*)k_gemm_mma<false,false,false>, cudaFuncAttributeMaxDynamicSharedMemorySize, SM);
    cudaFuncSetAttribute((const void*)k_gemm_mma<true,false,false>,  cudaFuncAttributeMaxDynamicSharedMemorySize, SM);

    dim3 gFused(GB, 6);   // y 0-1: gemm slices; y 2-5: CSR fill (3128 blocks)
    dim3 gBig(GB, 2);
    dim3 gSml(GB, 1);
    int aggBlocks = (NN*32 + 255)/256;

    // node 0: zero degree counters
    cudaMemsetAsync(pdeg, 0, NN*sizeof(int));
    // node 1: noise->x2 fp16 image + wconv + hist (fused)
    k_prep<<<NOISE_BLOCKS + WCONV_BLOCKS + HIST_BLOCKS, 256>>>(
        x, noise, ei, Wl0, Wr0, Wl1, Wr1, Wl2, Wr2);
    // node 2-3: scans
    k_scan1<<<NB_SCAN, 1024>>>();
    k_scan23<<<NB_SCAN, 1024>>>();
    // node 4: layer-0 GEMM + CSR fill fused (r written fp16)
    k_gemm_mma<false,true,true><<<gFused, 256, SM>>>((const uint8_t*)px2,
                                                     pw, pw + 65536, pt, pr, MM, ei);
    // layer 0 agg (r fp16) -> h1 fp16 image (g_h)
    k_agg128<<<aggBlocks, 256>>>((const uint32_t*)pt, pr, 1, bl0, (uint32_t*)ph, nullptr);
    // layer 1 (A from h1 image; r fp32); agg writes d_out fp32 + h2 fp16 image (g_x2)
    k_gemm_mma<false,false,false><<<gBig, 256, SM>>>((const uint8_t*)ph,
                                                     pw + 131072, pw + 196608, pt, pr, MM, nullptr);
    k_agg128<<<aggBlocks, 256>>>((const uint32_t*)pt, pr, 0, bl1, (uint32_t*)px2, out);
    // layer 2 (A from h2 image; t2 fp16 packed stride 24)
    k_gemm_mma<true,false,false><<<gSml, 256, SM>>>((const uint8_t*)px2,
                                                    pw + 262144, pw + 294912, pt2, pr2, MM, nullptr);
    k_agg47<<<aggBlocks, 256>>>((const uint32_t*)pt2, pr2, bl2, out);
}